// round 3
// baseline (speedup 1.0000x reference)
#include <cuda_runtime.h>

#define TMAX 4096
#define EMB  1152
#define NH   16
#define HD   72
#define E3   (3 * EMB)

// Scratch (allocation-free rule: __device__ globals)
__device__ float g_q[(size_t)NH * TMAX * HD];
__device__ float g_k[(size_t)NH * TMAX * HD];
__device__ float g_v[(size_t)NH * TMAX * HD];
__device__ float g_o[(size_t)TMAX * EMB];

// ---------------------------------------------------------------------------
// NT SGEMM: C[m][n] = sum_k A[m][k] * B[n][k] + bias[n]
// 128x128 tile, BK=8, 256 threads, 8x8 per thread, reg-prefetch pipeline.
// MODE 0: A = Ain (hidden states), epilogue scatters into g_q/g_k/g_v [h][t][d]
// MODE 1: A = g_o, epilogue writes C (d_out) with coalesced float4 stores
// ---------------------------------------------------------------------------
template <int MODE>
__global__ __launch_bounds__(256, 2)
void sgemm_nt(const float* __restrict__ Ain, const float* __restrict__ B,
              const float* __restrict__ bias, float* __restrict__ C,
              int M, int N, int K)
{
    const float* A = (MODE == 0) ? Ain : g_o;
    __shared__ float As[8][128];
    __shared__ float Bs[8][128];

    const int tid = threadIdx.x;
    const int tx = tid & 15, ty = tid >> 4;
    const int bm = blockIdx.y * 128, bn = blockIdx.x * 128;
    const int lr = tid >> 1;          // 0..127
    const int lc = (tid & 1) << 2;    // 0 or 4

    const float* Ap = A + (size_t)(bm + lr) * K + lc;
    const float* Bp = B + (size_t)(bn + lr) * K + lc;

    float acc[8][8];
#pragma unroll
    for (int i = 0; i < 8; i++)
#pragma unroll
        for (int j = 0; j < 8; j++) acc[i][j] = 0.f;

    float4 aReg = *(const float4*)Ap;
    float4 bReg = *(const float4*)Bp;

    const int nt = K >> 3;
    for (int kt = 0; kt < nt; kt++) {
        __syncthreads();
        As[lc + 0][lr] = aReg.x;
        As[lc + 1][lr] = aReg.y;
        As[lc + 2][lr] = aReg.z;
        As[lc + 3][lr] = aReg.w;
        Bs[lc + 0][lr] = bReg.x;
        Bs[lc + 1][lr] = bReg.y;
        Bs[lc + 2][lr] = bReg.z;
        Bs[lc + 3][lr] = bReg.w;
        __syncthreads();
        if (kt + 1 < nt) {
            aReg = *(const float4*)(Ap + (size_t)(kt + 1) * 8);
            bReg = *(const float4*)(Bp + (size_t)(kt + 1) * 8);
        }
#pragma unroll
        for (int kk = 0; kk < 8; kk++) {
            float a[8], b[8];
            *(float4*)&a[0] = *(const float4*)&As[kk][ty * 8];
            *(float4*)&a[4] = *(const float4*)&As[kk][ty * 8 + 4];
            *(float4*)&b[0] = *(const float4*)&Bs[kk][tx * 8];
            *(float4*)&b[4] = *(const float4*)&Bs[kk][tx * 8 + 4];
#pragma unroll
            for (int i = 0; i < 8; i++)
#pragma unroll
                for (int j = 0; j < 8; j++)
                    acc[i][j] += a[i] * b[j];
        }
    }

#pragma unroll
    for (int i = 0; i < 8; i++) {
        const int row = bm + ty * 8 + i;
#pragma unroll
        for (int jj = 0; jj < 2; jj++) {
            const int col = bn + tx * 8 + jj * 4;
            float4 v;
            v.x = acc[i][jj * 4 + 0] + bias[col + 0];
            v.y = acc[i][jj * 4 + 1] + bias[col + 1];
            v.z = acc[i][jj * 4 + 2] + bias[col + 2];
            v.w = acc[i][jj * 4 + 3] + bias[col + 3];
            if (MODE == 1) {
                *(float4*)&C[(size_t)row * N + col] = v;
            } else {
                const int which = col / EMB;
                const int r = col - which * EMB;
                const int h = r / HD;
                const int d = r - h * HD;
                float* dst = (which == 0) ? g_q : (which == 1) ? g_k : g_v;
                *(float4*)&dst[((size_t)h * M + row) * HD + d] = v;
            }
        }
    }
}

// ---------------------------------------------------------------------------
// Flash-style varlen attention.
// Grid: (q_tiles, NH, n_seq). CTA: 256 threads, 64 query rows.
// S-phase: 16x16 threads, 4x4 microtile, float4 smem operands.
// O-phase: 64 rows x 4 column-groups (D padded to 80), 20 accumulators/thread.
// ---------------------------------------------------------------------------
__global__ __launch_bounds__(256, 2)
void attn_kernel(const int* __restrict__ cu, int T)
{
    extern __shared__ float sm[];
    float* Qs     = sm;                  // 64 * 76
    float* Ks     = Qs + 64 * 76;        // 64 * 76
    float* Vs     = Ks + 64 * 76;        // 64 * 80 (cols 72..79 zero)
    float* Ps     = Vs + 64 * 80;        // 64 * 68
    float* rAlpha = Ps + 64 * 68;        // 64
    float* rL     = rAlpha + 64;         // 64

    const int seq = blockIdx.z;
    const int h   = blockIdx.y;
    const int s0  = cu[seq];
    const int L   = cu[seq + 1] - s0;
    const int q0  = blockIdx.x * 64;
    if (q0 >= L) return;

    const int tid = threadIdx.x;
    const int tx = tid & 15, ty = tid >> 4;
    const int orow = tid >> 2, og = tid & 3;
    const float scale = 0.11785113019775793f; // 72^-0.5

    const float* Qg = g_q + (size_t)h * T * HD;
    const float* Kg = g_k + (size_t)h * T * HD;
    const float* Vg = g_v + (size_t)h * T * HD;

    // Load Q tile (pre-scaled), zero-pad invalid rows
    for (int t = tid; t < 64 * 18; t += 256) {
        const int r = t / 18, c = (t - r * 18) * 4;
        float4 v = make_float4(0.f, 0.f, 0.f, 0.f);
        if (q0 + r < L) v = *(const float4*)(Qg + (size_t)(s0 + q0 + r) * HD + c);
        v.x *= scale; v.y *= scale; v.z *= scale; v.w *= scale;
        *(float4*)(Qs + r * 76 + c) = v;
    }
    // Zero V pad columns 72..79
    if (tid < 128) {
        const int r = tid >> 1, c = 72 + (tid & 1) * 4;
        *(float4*)(Vs + r * 80 + c) = make_float4(0.f, 0.f, 0.f, 0.f);
    }

    float m_run[4], l_run[4];
#pragma unroll
    for (int i = 0; i < 4; i++) { m_run[i] = -1e30f; l_run[i] = 0.f; }
    float oacc[20];
#pragma unroll
    for (int c = 0; c < 20; c++) oacc[c] = 0.f;

    const int nkt = (L + 63) >> 6;
    for (int kt = 0; kt < nkt; kt++) {
        const int k0 = kt * 64;
        __syncthreads();  // protect Vs/Ps from previous iteration's readers

        // Stage K/V tile (zero-fill rows beyond L)
        for (int t = tid; t < 64 * 18; t += 256) {
            const int r = t / 18, c = (t - r * 18) * 4;
            float4 kv = make_float4(0.f, 0.f, 0.f, 0.f);
            float4 vv = kv;
            if (k0 + r < L) {
                const size_t off = (size_t)(s0 + k0 + r) * HD + c;
                kv = *(const float4*)(Kg + off);
                vv = *(const float4*)(Vg + off);
            }
            *(float4*)(Ks + r * 76 + c) = kv;
            *(float4*)(Vs + r * 80 + c) = vv;
        }
        __syncthreads();

        // S = Q K^T (scaled)
        float s[4][4];
#pragma unroll
        for (int i = 0; i < 4; i++)
#pragma unroll
            for (int j = 0; j < 4; j++) s[i][j] = 0.f;

        const float4* Q4 = (const float4*)Qs;  // stride 19
        const float4* K4 = (const float4*)Ks;  // stride 19
#pragma unroll 3
        for (int d4 = 0; d4 < 18; d4++) {
            float4 a[4], b[4];
#pragma unroll
            for (int i = 0; i < 4; i++) a[i] = Q4[(ty * 4 + i) * 19 + d4];
#pragma unroll
            for (int j = 0; j < 4; j++) b[j] = K4[(tx * 4 + j) * 19 + d4];
#pragma unroll
            for (int i = 0; i < 4; i++)
#pragma unroll
                for (int j = 0; j < 4; j++) {
                    s[i][j] += a[i].x * b[j].x;
                    s[i][j] += a[i].y * b[j].y;
                    s[i][j] += a[i].z * b[j].z;
                    s[i][j] += a[i].w * b[j].w;
                }
        }

        // Online softmax (row groups = 16 consecutive lanes)
#pragma unroll
        for (int i = 0; i < 4; i++) {
            float mloc = -1e30f;
#pragma unroll
            for (int j = 0; j < 4; j++) {
                if (k0 + tx * 4 + j >= L) s[i][j] = -1e30f;
                mloc = fmaxf(mloc, s[i][j]);
            }
#pragma unroll
            for (int off = 8; off > 0; off >>= 1)
                mloc = fmaxf(mloc, __shfl_xor_sync(0xffffffffu, mloc, off));
            const float mn = fmaxf(m_run[i], mloc);
            const float alpha = __expf(m_run[i] - mn);
            float ls = 0.f;
#pragma unroll
            for (int j = 0; j < 4; j++) {
                const float p = __expf(s[i][j] - mn);
                s[i][j] = p;
                ls += p;
            }
#pragma unroll
            for (int off = 8; off > 0; off >>= 1)
                ls += __shfl_xor_sync(0xffffffffu, ls, off);
            l_run[i] = l_run[i] * alpha + ls;
            m_run[i] = mn;
            if (tx == 0) rAlpha[ty * 4 + i] = alpha;
            *(float4*)&Ps[(ty * 4 + i) * 68 + tx * 4] = *(float4*)&s[i][0];
        }
        __syncthreads();

        // O = O*alpha + P V
        {
            const float alpha = rAlpha[orow];
#pragma unroll
            for (int c = 0; c < 20; c++) oacc[c] *= alpha;
            const float* prow = Ps + orow * 68;
            const float4* V4 = (const float4*)Vs;   // stride 20
            const int cb = og * 5;
#pragma unroll 2
            for (int j = 0; j < 64; j++) {
                const float p = prow[j];
                const float4 v0 = V4[j * 20 + cb + 0];
                const float4 v1 = V4[j * 20 + cb + 1];
                const float4 v2 = V4[j * 20 + cb + 2];
                const float4 v3 = V4[j * 20 + cb + 3];
                const float4 v4 = V4[j * 20 + cb + 4];
                oacc[0]  += p * v0.x; oacc[1]  += p * v0.y; oacc[2]  += p * v0.z; oacc[3]  += p * v0.w;
                oacc[4]  += p * v1.x; oacc[5]  += p * v1.y; oacc[6]  += p * v1.z; oacc[7]  += p * v1.w;
                oacc[8]  += p * v2.x; oacc[9]  += p * v2.y; oacc[10] += p * v2.z; oacc[11] += p * v2.w;
                oacc[12] += p * v3.x; oacc[13] += p * v3.y; oacc[14] += p * v3.z; oacc[15] += p * v3.w;
                oacc[16] += p * v4.x; oacc[17] += p * v4.y; oacc[18] += p * v4.z; oacc[19] += p * v4.w;
            }
        }
    }

    // Publish per-row softmax denominators, then normalize + store O
    if (tx == 0) {
#pragma unroll
        for (int i = 0; i < 4; i++) rL[ty * 4 + i] = l_run[i];
    }
    __syncthreads();

    if (q0 + orow < L) {
        const float inv = 1.f / rL[orow];
        float* Og = g_o + (size_t)(s0 + q0 + orow) * EMB + h * HD + og * 20;
        const int nf4 = (og == 3) ? 3 : 5;  // last group only 12 valid of 20
#pragma unroll
        for (int c4 = 0; c4 < 5; c4++) {
            if (c4 < nf4) {
                float4 v;
                v.x = oacc[c4 * 4 + 0] * inv;
                v.y = oacc[c4 * 4 + 1] * inv;
                v.z = oacc[c4 * 4 + 2] * inv;
                v.w = oacc[c4 * 4 + 3] * inv;
                *(float4*)(Og + c4 * 4) = v;
            }
        }
    }
}

// ---------------------------------------------------------------------------
extern "C" void kernel_launch(void* const* d_in, const int* in_sizes, int n_in,
                              void* d_out, int out_size)
{
    const float* x    = (const float*)d_in[0];
    const float* wqkv = (const float*)d_in[1];
    const float* bqkv = (const float*)d_in[2];
    const float* wout = (const float*)d_in[3];
    const float* bout = (const float*)d_in[4];
    const int*   cu   = (const int*)d_in[5];

    const int T = in_sizes[0] / EMB;      // 4096
    const int nseq = in_sizes[5] - 1;     // 8

    const int SMEM_ATTN = (64 * 76 * 2 + 64 * 80 + 64 * 68 + 128) * (int)sizeof(float);
    cudaFuncSetAttribute(attn_kernel, cudaFuncAttributeMaxDynamicSharedMemorySize, SMEM_ATTN);

    dim3 blk(256);

    // 1) fused QKV projection + scatter to [h][t][d]
    dim3 g1(E3 / 128, T / 128);
    sgemm_nt<0><<<g1, blk>>>(x, wqkv, bqkv, nullptr, T, E3, EMB);

    // 2) block-diagonal varlen attention -> g_o [t][e]
    dim3 ga((T + 63) / 64, NH, nseq);
    attn_kernel<<<ga, blk, SMEM_ATTN>>>(cu, T);

    // 3) output projection -> d_out
    dim3 g2(EMB / 128, T / 128);
    sgemm_nt<1><<<g2, blk>>>(nullptr, wout, bout, (float*)d_out, T, EMB, EMB);
}

// round 4
// speedup vs baseline: 1.0003x; 1.0003x over previous
#include <cuda_runtime.h>

#define TMAX 4096
#define EMB  1152
#define NH   16
#define HD   72
#define E3   (3 * EMB)

// Scratch (allocation-free rule: __device__ globals)
__device__ float g_q[(size_t)NH * TMAX * HD];
__device__ float g_k[(size_t)NH * TMAX * HD];
__device__ float g_v[(size_t)NH * TMAX * HD];
__device__ float g_o[(size_t)TMAX * EMB];

// ---------------------------------------------------------------------------
// NT SGEMM: C[m][n] = sum_k A[m][k] * B[n][k] + bias[n]
// 128x128 tile, BK=8, 256 threads, 8x8 per thread, reg-prefetch pipeline.
// MODE 0: A = Ain (hidden states), epilogue scatters into g_q/g_k/g_v [h][t][d]
// MODE 1: A = g_o, epilogue writes C (d_out) with coalesced float4 stores
// ---------------------------------------------------------------------------
template <int MODE>
__global__ __launch_bounds__(256, 2)
void sgemm_nt(const float* __restrict__ Ain, const float* __restrict__ B,
              const float* __restrict__ bias, float* __restrict__ C,
              int M, int N, int K)
{
    const float* A = (MODE == 0) ? Ain : g_o;
    __shared__ float As[8][128];
    __shared__ float Bs[8][128];

    const int tid = threadIdx.x;
    const int tx = tid & 15, ty = tid >> 4;
    const int bm = blockIdx.y * 128, bn = blockIdx.x * 128;
    const int lr = tid >> 1;          // 0..127
    const int lc = (tid & 1) << 2;    // 0 or 4

    const float* Ap = A + (size_t)(bm + lr) * K + lc;
    const float* Bp = B + (size_t)(bn + lr) * K + lc;

    float acc[8][8];
#pragma unroll
    for (int i = 0; i < 8; i++)
#pragma unroll
        for (int j = 0; j < 8; j++) acc[i][j] = 0.f;

    float4 aReg = *(const float4*)Ap;
    float4 bReg = *(const float4*)Bp;

    const int nt = K >> 3;
    for (int kt = 0; kt < nt; kt++) {
        __syncthreads();
        As[lc + 0][lr] = aReg.x;
        As[lc + 1][lr] = aReg.y;
        As[lc + 2][lr] = aReg.z;
        As[lc + 3][lr] = aReg.w;
        Bs[lc + 0][lr] = bReg.x;
        Bs[lc + 1][lr] = bReg.y;
        Bs[lc + 2][lr] = bReg.z;
        Bs[lc + 3][lr] = bReg.w;
        __syncthreads();
        if (kt + 1 < nt) {
            aReg = *(const float4*)(Ap + (size_t)(kt + 1) * 8);
            bReg = *(const float4*)(Bp + (size_t)(kt + 1) * 8);
        }
#pragma unroll
        for (int kk = 0; kk < 8; kk++) {
            float a[8], b[8];
            *(float4*)&a[0] = *(const float4*)&As[kk][ty * 8];
            *(float4*)&a[4] = *(const float4*)&As[kk][ty * 8 + 4];
            *(float4*)&b[0] = *(const float4*)&Bs[kk][tx * 8];
            *(float4*)&b[4] = *(const float4*)&Bs[kk][tx * 8 + 4];
#pragma unroll
            for (int i = 0; i < 8; i++)
#pragma unroll
                for (int j = 0; j < 8; j++)
                    acc[i][j] += a[i] * b[j];
        }
    }

#pragma unroll
    for (int i = 0; i < 8; i++) {
        const int row = bm + ty * 8 + i;
#pragma unroll
        for (int jj = 0; jj < 2; jj++) {
            const int col = bn + tx * 8 + jj * 4;
            float4 v;
            v.x = acc[i][jj * 4 + 0] + bias[col + 0];
            v.y = acc[i][jj * 4 + 1] + bias[col + 1];
            v.z = acc[i][jj * 4 + 2] + bias[col + 2];
            v.w = acc[i][jj * 4 + 3] + bias[col + 3];
            if (MODE == 1) {
                *(float4*)&C[(size_t)row * N + col] = v;
            } else {
                const int which = col / EMB;
                const int r = col - which * EMB;
                const int h = r / HD;
                const int d = r - h * HD;
                float* dst = (which == 0) ? g_q : (which == 1) ? g_k : g_v;
                *(float4*)&dst[((size_t)h * M + row) * HD + d] = v;
            }
        }
    }
}

// ---------------------------------------------------------------------------
// Flash-style varlen attention.
// Grid: (q_tiles, NH, n_seq). CTA: 256 threads, 64 query rows.
// S-phase: 16x16 threads, 4x4 microtile, float4 smem operands.
// O-phase: 64 rows x 4 column-groups (D padded to 80), 20 accumulators/thread.
// ---------------------------------------------------------------------------
__global__ __launch_bounds__(256, 2)
void attn_kernel(const int* __restrict__ cu, int T)
{
    extern __shared__ float sm[];
    float* Qs     = sm;                  // 64 * 76
    float* Ks     = Qs + 64 * 76;        // 64 * 76
    float* Vs     = Ks + 64 * 76;        // 64 * 80 (cols 72..79 zero)
    float* Ps     = Vs + 64 * 80;        // 64 * 68
    float* rAlpha = Ps + 64 * 68;        // 64
    float* rL     = rAlpha + 64;         // 64

    const int seq = blockIdx.z;
    const int h   = blockIdx.y;
    const int s0  = cu[seq];
    const int L   = cu[seq + 1] - s0;
    const int q0  = blockIdx.x * 64;
    if (q0 >= L) return;

    const int tid = threadIdx.x;
    const int tx = tid & 15, ty = tid >> 4;
    const int orow = tid >> 2, og = tid & 3;
    const float scale = 0.11785113019775793f; // 72^-0.5

    const float* Qg = g_q + (size_t)h * T * HD;
    const float* Kg = g_k + (size_t)h * T * HD;
    const float* Vg = g_v + (size_t)h * T * HD;

    // Load Q tile (pre-scaled), zero-pad invalid rows
    for (int t = tid; t < 64 * 18; t += 256) {
        const int r = t / 18, c = (t - r * 18) * 4;
        float4 v = make_float4(0.f, 0.f, 0.f, 0.f);
        if (q0 + r < L) v = *(const float4*)(Qg + (size_t)(s0 + q0 + r) * HD + c);
        v.x *= scale; v.y *= scale; v.z *= scale; v.w *= scale;
        *(float4*)(Qs + r * 76 + c) = v;
    }
    // Zero V pad columns 72..79
    if (tid < 128) {
        const int r = tid >> 1, c = 72 + (tid & 1) * 4;
        *(float4*)(Vs + r * 80 + c) = make_float4(0.f, 0.f, 0.f, 0.f);
    }

    float m_run[4], l_run[4];
#pragma unroll
    for (int i = 0; i < 4; i++) { m_run[i] = -1e30f; l_run[i] = 0.f; }
    float oacc[20];
#pragma unroll
    for (int c = 0; c < 20; c++) oacc[c] = 0.f;

    const int nkt = (L + 63) >> 6;
    for (int kt = 0; kt < nkt; kt++) {
        const int k0 = kt * 64;
        __syncthreads();  // protect Vs/Ps from previous iteration's readers

        // Stage K/V tile (zero-fill rows beyond L)
        for (int t = tid; t < 64 * 18; t += 256) {
            const int r = t / 18, c = (t - r * 18) * 4;
            float4 kv = make_float4(0.f, 0.f, 0.f, 0.f);
            float4 vv = kv;
            if (k0 + r < L) {
                const size_t off = (size_t)(s0 + k0 + r) * HD + c;
                kv = *(const float4*)(Kg + off);
                vv = *(const float4*)(Vg + off);
            }
            *(float4*)(Ks + r * 76 + c) = kv;
            *(float4*)(Vs + r * 80 + c) = vv;
        }
        __syncthreads();

        // S = Q K^T (scaled)
        float s[4][4];
#pragma unroll
        for (int i = 0; i < 4; i++)
#pragma unroll
            for (int j = 0; j < 4; j++) s[i][j] = 0.f;

        const float4* Q4 = (const float4*)Qs;  // stride 19
        const float4* K4 = (const float4*)Ks;  // stride 19
#pragma unroll 3
        for (int d4 = 0; d4 < 18; d4++) {
            float4 a[4], b[4];
#pragma unroll
            for (int i = 0; i < 4; i++) a[i] = Q4[(ty * 4 + i) * 19 + d4];
#pragma unroll
            for (int j = 0; j < 4; j++) b[j] = K4[(tx * 4 + j) * 19 + d4];
#pragma unroll
            for (int i = 0; i < 4; i++)
#pragma unroll
                for (int j = 0; j < 4; j++) {
                    s[i][j] += a[i].x * b[j].x;
                    s[i][j] += a[i].y * b[j].y;
                    s[i][j] += a[i].z * b[j].z;
                    s[i][j] += a[i].w * b[j].w;
                }
        }

        // Online softmax (row groups = 16 consecutive lanes)
#pragma unroll
        for (int i = 0; i < 4; i++) {
            float mloc = -1e30f;
#pragma unroll
            for (int j = 0; j < 4; j++) {
                if (k0 + tx * 4 + j >= L) s[i][j] = -1e30f;
                mloc = fmaxf(mloc, s[i][j]);
            }
#pragma unroll
            for (int off = 8; off > 0; off >>= 1)
                mloc = fmaxf(mloc, __shfl_xor_sync(0xffffffffu, mloc, off));
            const float mn = fmaxf(m_run[i], mloc);
            const float alpha = __expf(m_run[i] - mn);
            float ls = 0.f;
#pragma unroll
            for (int j = 0; j < 4; j++) {
                const float p = __expf(s[i][j] - mn);
                s[i][j] = p;
                ls += p;
            }
#pragma unroll
            for (int off = 8; off > 0; off >>= 1)
                ls += __shfl_xor_sync(0xffffffffu, ls, off);
            l_run[i] = l_run[i] * alpha + ls;
            m_run[i] = mn;
            if (tx == 0) rAlpha[ty * 4 + i] = alpha;
            *(float4*)&Ps[(ty * 4 + i) * 68 + tx * 4] = *(float4*)&s[i][0];
        }
        __syncthreads();

        // O = O*alpha + P V
        {
            const float alpha = rAlpha[orow];
#pragma unroll
            for (int c = 0; c < 20; c++) oacc[c] *= alpha;
            const float* prow = Ps + orow * 68;
            const float4* V4 = (const float4*)Vs;   // stride 20
            const int cb = og * 5;
#pragma unroll 2
            for (int j = 0; j < 64; j++) {
                const float p = prow[j];
                const float4 v0 = V4[j * 20 + cb + 0];
                const float4 v1 = V4[j * 20 + cb + 1];
                const float4 v2 = V4[j * 20 + cb + 2];
                const float4 v3 = V4[j * 20 + cb + 3];
                const float4 v4 = V4[j * 20 + cb + 4];
                oacc[0]  += p * v0.x; oacc[1]  += p * v0.y; oacc[2]  += p * v0.z; oacc[3]  += p * v0.w;
                oacc[4]  += p * v1.x; oacc[5]  += p * v1.y; oacc[6]  += p * v1.z; oacc[7]  += p * v1.w;
                oacc[8]  += p * v2.x; oacc[9]  += p * v2.y; oacc[10] += p * v2.z; oacc[11] += p * v2.w;
                oacc[12] += p * v3.x; oacc[13] += p * v3.y; oacc[14] += p * v3.z; oacc[15] += p * v3.w;
                oacc[16] += p * v4.x; oacc[17] += p * v4.y; oacc[18] += p * v4.z; oacc[19] += p * v4.w;
            }
        }
    }

    // Publish per-row softmax denominators, then normalize + store O
    if (tx == 0) {
#pragma unroll
        for (int i = 0; i < 4; i++) rL[ty * 4 + i] = l_run[i];
    }
    __syncthreads();

    if (q0 + orow < L) {
        const float inv = 1.f / rL[orow];
        float* Og = g_o + (size_t)(s0 + q0 + orow) * EMB + h * HD + og * 20;
        const int nf4 = (og == 3) ? 3 : 5;  // last group only 12 valid of 20
#pragma unroll
        for (int c4 = 0; c4 < 5; c4++) {
            if (c4 < nf4) {
                float4 v;
                v.x = oacc[c4 * 4 + 0] * inv;
                v.y = oacc[c4 * 4 + 1] * inv;
                v.z = oacc[c4 * 4 + 2] * inv;
                v.w = oacc[c4 * 4 + 3] * inv;
                *(float4*)(Og + c4 * 4) = v;
            }
        }
    }
}

// ---------------------------------------------------------------------------
extern "C" void kernel_launch(void* const* d_in, const int* in_sizes, int n_in,
                              void* d_out, int out_size)
{
    const float* x    = (const float*)d_in[0];
    const float* wqkv = (const float*)d_in[1];
    const float* bqkv = (const float*)d_in[2];
    const float* wout = (const float*)d_in[3];
    const float* bout = (const float*)d_in[4];
    const int*   cu   = (const int*)d_in[5];

    const int T = in_sizes[0] / EMB;      // 4096
    const int nseq = in_sizes[5] - 1;     // 8

    const int SMEM_ATTN = (64 * 76 * 2 + 64 * 80 + 64 * 68 + 128) * (int)sizeof(float);
    cudaFuncSetAttribute(attn_kernel, cudaFuncAttributeMaxDynamicSharedMemorySize, SMEM_ATTN);

    dim3 blk(256);

    // 1) fused QKV projection + scatter to [h][t][d]
    dim3 g1(E3 / 128, T / 128);
    sgemm_nt<0><<<g1, blk>>>(x, wqkv, bqkv, nullptr, T, E3, EMB);

    // 2) block-diagonal varlen attention -> g_o [t][e]
    dim3 ga((T + 63) / 64, NH, nseq);
    attn_kernel<<<ga, blk, SMEM_ATTN>>>(cu, T);

    // 3) output projection -> d_out
    dim3 g2(EMB / 128, T / 128);
    sgemm_nt<1><<<g2, blk>>>(nullptr, wout, bout, (float*)d_out, T, EMB, EMB);
}

// round 8
// speedup vs baseline: 1.5067x; 1.5063x over previous
#include <cuda_runtime.h>
#include <cuda_bf16.h>
#include <cstdint>

#define TMAX 4096
#define EMB  1152
#define NH   16
#define HD   72
#define E3   (3 * EMB)

// ---------------- scratch (__device__ globals; allocation-free rule) -------
__device__ float g_q[(size_t)NH * TMAX * HD];
__device__ float g_k[(size_t)NH * TMAX * HD];
__device__ float g_v[(size_t)NH * TMAX * HD];
__device__ float g_o[(size_t)TMAX * EMB];

__device__ unsigned short g_xh[(size_t)TMAX * EMB];
__device__ unsigned short g_xl[(size_t)TMAX * EMB];
__device__ unsigned short g_w1h[(size_t)E3 * EMB];
__device__ unsigned short g_w1l[(size_t)E3 * EMB];
__device__ unsigned short g_w2h[(size_t)EMB * EMB];
__device__ unsigned short g_w2l[(size_t)EMB * EMB];
__device__ unsigned short g_oh[(size_t)TMAX * EMB];
__device__ unsigned short g_ol[(size_t)TMAX * EMB];

// ---------------- base-PTX helpers (NO tcgen05 — target is compute_103) ----
__device__ __forceinline__ uint32_t smem_u32(const void* p) {
    uint32_t a;
    asm("{ .reg .u64 t; cvta.to.shared.u64 t, %1; cvt.u32.u64 %0, t; }"
        : "=r"(a) : "l"(p));
    return a;
}

__device__ __forceinline__ void cp16(uint32_t dst, const void* src) {
    asm volatile("cp.async.cg.shared.global [%0], [%1], 16;"
                 :: "r"(dst), "l"(src) : "memory");
}
#define CP_COMMIT() asm volatile("cp.async.commit_group;" ::: "memory")
#define CP_WAIT0()  asm volatile("cp.async.wait_group 0;" ::: "memory")

__device__ __forceinline__ void ldm4(uint32_t addr, uint32_t& r0, uint32_t& r1,
                                     uint32_t& r2, uint32_t& r3) {
    asm volatile("ldmatrix.sync.aligned.m8n8.x4.shared.b16 {%0,%1,%2,%3}, [%4];"
                 : "=r"(r0), "=r"(r1), "=r"(r2), "=r"(r3) : "r"(addr));
}

__device__ __forceinline__ void mma_bf16(float& c0, float& c1, float& c2, float& c3,
                                         uint32_t a0, uint32_t a1, uint32_t a2, uint32_t a3,
                                         uint32_t b0, uint32_t b1) {
    asm volatile(
        "mma.sync.aligned.m16n8k16.row.col.f32.bf16.bf16.f32 "
        "{%0,%1,%2,%3}, {%4,%5,%6,%7}, {%8,%9}, {%0,%1,%2,%3};"
        : "+f"(c0), "+f"(c1), "+f"(c2), "+f"(c3)
        : "r"(a0), "r"(a1), "r"(a2), "r"(a3), "r"(b0), "r"(b1));
}

// ---------------------------------------------------------------------------
// fp32 -> (bf16 hi, bf16 lo) split conversion.  WHICH: 0=x, 1=wqkv, 2=wout, 3=g_o
// ---------------------------------------------------------------------------
template <int WHICH>
__global__ void cvt_split(const float4* __restrict__ srcIn, int n4)
{
    int i = blockIdx.x * blockDim.x + threadIdx.x;
    if (i >= n4) return;
    unsigned short* hi;
    unsigned short* lo;
    const float4* src = srcIn;
    if (WHICH == 0)      { hi = g_xh;  lo = g_xl;  }
    else if (WHICH == 1) { hi = g_w1h; lo = g_w1l; }
    else if (WHICH == 2) { hi = g_w2h; lo = g_w2l; }
    else                 { hi = g_oh;  lo = g_ol;  src = (const float4*)g_o; }

    float4 v = src[i];
    float f[4] = {v.x, v.y, v.z, v.w};
    unsigned short h[4], l[4];
#pragma unroll
    for (int j = 0; j < 4; j++) {
        __nv_bfloat16 hb = __float2bfloat16(f[j]);
        h[j] = __bfloat16_as_ushort(hb);
        float r = f[j] - __bfloat162float(hb);
        l[j] = __bfloat16_as_ushort(__float2bfloat16(r));
    }
    ((ushort4*)hi)[i] = make_ushort4(h[0], h[1], h[2], h[3]);
    ((ushort4*)lo)[i] = make_ushort4(l[0], l[1], l[2], l[3]);
}

// ---------------------------------------------------------------------------
// bf16-split NT GEMM via mma.sync (base-PTX tensor cores).
//   C[m][n] = sum_k A[m][k]*B[n][k] + bias[n]
// CTA 128x128, 8 warps (2 m-halves x 4 n-quarters), warp tile 64x32.
// K chunked by 64; Ah/Al/Bh/Bl staged in smem (rows padded to 72 bf16 = 144B,
// ldmatrix conflict-free), double-buffered via cp.async.
// MODE 0: A=x(hi/lo), B=wqkv(hi/lo), epilogue scatters Q/K/V [h][t][d]
// MODE 1: A=g_o(hi/lo), B=wout(hi/lo), epilogue stores C row-major
// ---------------------------------------------------------------------------
#define ROWB   144          // bytes per smem row (72 bf16)
#define MATB   18432        // 128 * 144 bytes per matrix tile
#define STAGEB 73728        // 4 matrices per stage

template <int MODE>
__global__ __launch_bounds__(256)
void tc_gemm(const float* __restrict__ bias, float* __restrict__ C,
             int M, int N, int K)
{
    extern __shared__ char smem[];
    const uint32_t sb = smem_u32(smem);
    const int tid  = threadIdx.x;
    const int wid  = tid >> 5, lane = tid & 31;
    const int wm   = wid & 1;        // 0..1  (64 rows each)
    const int wn   = wid >> 1;       // 0..3  (32 cols each)
    const int bm = blockIdx.y * 128, bn = blockIdx.x * 128;

    const unsigned short* Ah = (MODE == 0) ? g_xh  : g_oh;
    const unsigned short* Al = (MODE == 0) ? g_xl  : g_ol;
    const unsigned short* Bh = (MODE == 0) ? g_w1h : g_w2h;
    const unsigned short* Bl = (MODE == 0) ? g_w1l : g_w2l;

    // per-lane ldmatrix row/col components
    const int la_row = lane & 15;              // A: row within 16-tile
    const int la_k   = (lane >> 4) * 8;        // A: k offset 0/8
    const int lb_n   = (lane & 7) + ((lane >> 4) & 1) * 8;  // B: n within 16
    const int lb_k   = ((lane >> 3) & 1) * 8;  // B: k offset 0/8

    float c[4][4][4];
#pragma unroll
    for (int i = 0; i < 4; i++)
#pragma unroll
        for (int j = 0; j < 4; j++)
#pragma unroll
            for (int r = 0; r < 4; r++) c[i][j][r] = 0.f;

    const int nc = K >> 6;  // 64-K chunks

    // ---- async stage of chunk kc into buffer st ----
    auto issue = [&](int kc, uint32_t stBase) {
        const int c0 = kc << 6;
#pragma unroll
        for (int it = 0; it < 4; it++) {
            const int idx = it * 256 + tid;       // 0..1023
            const int row = idx >> 3, ch = idx & 7;
            const uint32_t doff = (uint32_t)row * ROWB + ch * 16;
            cp16(stBase + 0 * MATB + doff, Ah + (size_t)(bm + row) * K + c0 + ch * 8);
            cp16(stBase + 1 * MATB + doff, Al + (size_t)(bm + row) * K + c0 + ch * 8);
            cp16(stBase + 2 * MATB + doff, Bh + (size_t)(bn + row) * K + c0 + ch * 8);
            cp16(stBase + 3 * MATB + doff, Bl + (size_t)(bn + row) * K + c0 + ch * 8);
        }
        CP_COMMIT();
    };

    issue(0, sb);

    for (int kc = 0; kc < nc; kc++) {
        CP_WAIT0();
        __syncthreads();
        if (kc + 1 < nc) issue(kc + 1, sb + ((kc + 1) & 1) * STAGEB);

        const uint32_t st  = sb + (kc & 1) * STAGEB;
        const uint32_t stAh = st;
        const uint32_t stAl = st + MATB;
        const uint32_t stBh = st + 2 * MATB;
        const uint32_t stBl = st + 3 * MATB;

#pragma unroll
        for (int ks = 0; ks < 4; ks++) {
            const int k0 = ks * 16;
            uint32_t ah[4][4], al[4][4], bh[2][4], bl[2][4];
#pragma unroll
            for (int mt = 0; mt < 4; mt++) {
                const uint32_t ra = (uint32_t)(wm * 64 + mt * 16 + la_row) * ROWB
                                  + (uint32_t)(k0 + la_k) * 2;
                ldm4(stAh + ra, ah[mt][0], ah[mt][1], ah[mt][2], ah[mt][3]);
                ldm4(stAl + ra, al[mt][0], al[mt][1], al[mt][2], al[mt][3]);
            }
#pragma unroll
            for (int np = 0; np < 2; np++) {
                const uint32_t rb = (uint32_t)(wn * 32 + np * 16 + lb_n) * ROWB
                                  + (uint32_t)(k0 + lb_k) * 2;
                ldm4(stBh + rb, bh[np][0], bh[np][1], bh[np][2], bh[np][3]);
                ldm4(stBl + rb, bl[np][0], bl[np][1], bl[np][2], bl[np][3]);
            }
#pragma unroll
            for (int mt = 0; mt < 4; mt++)
#pragma unroll
                for (int nt = 0; nt < 4; nt++) {
                    const int np = nt >> 1, jo = (nt & 1) * 2;
                    float* cc = c[mt][nt];
                    mma_bf16(cc[0], cc[1], cc[2], cc[3],
                             ah[mt][0], ah[mt][1], ah[mt][2], ah[mt][3],
                             bh[np][jo], bh[np][jo + 1]);
                    mma_bf16(cc[0], cc[1], cc[2], cc[3],
                             ah[mt][0], ah[mt][1], ah[mt][2], ah[mt][3],
                             bl[np][jo], bl[np][jo + 1]);
                    mma_bf16(cc[0], cc[1], cc[2], cc[3],
                             al[mt][0], al[mt][1], al[mt][2], al[mt][3],
                             bh[np][jo], bh[np][jo + 1]);
                }
        }
        __syncthreads();
    }

    // ---- epilogue: +bias, store (row pairs per accumulator reg pair) ----
    const int gid = lane >> 2, qid = lane & 3;
#pragma unroll
    for (int mt = 0; mt < 4; mt++) {
        const int row0 = bm + wm * 64 + mt * 16 + gid;
#pragma unroll
        for (int nt = 0; nt < 4; nt++) {
            const int col = bn + wn * 32 + nt * 8 + qid * 2;
            const float bx = bias[col], by = bias[col + 1];
            float2 v0 = make_float2(c[mt][nt][0] + bx, c[mt][nt][1] + by);
            float2 v1 = make_float2(c[mt][nt][2] + bx, c[mt][nt][3] + by);
            if (MODE == 1) {
                *(float2*)&C[(size_t)row0 * N + col] = v0;
                *(float2*)&C[(size_t)(row0 + 8) * N + col] = v1;
            } else {
                const int which = col / EMB;
                const int r = col - which * EMB;
                const int h = r / HD;
                const int d = r - h * HD;
                float* dst = (which == 0) ? g_q : (which == 1) ? g_k : g_v;
                *(float2*)&dst[((size_t)h * M + row0) * HD + d] = v0;
                *(float2*)&dst[((size_t)h * M + row0 + 8) * HD + d] = v1;
            }
        }
    }
}

// ---------------------------------------------------------------------------
// Flash-style varlen attention (unchanged from passing R3 kernel).
// ---------------------------------------------------------------------------
__global__ __launch_bounds__(256, 2)
void attn_kernel(const int* __restrict__ cu, int T)
{
    extern __shared__ float sm[];
    float* Qs     = sm;                  // 64 * 76
    float* Ks     = Qs + 64 * 76;        // 64 * 76
    float* Vs     = Ks + 64 * 76;        // 64 * 80 (cols 72..79 zero)
    float* Ps     = Vs + 64 * 80;        // 64 * 68
    float* rAlpha = Ps + 64 * 68;        // 64
    float* rL     = rAlpha + 64;         // 64

    const int seq = blockIdx.z;
    const int h   = blockIdx.y;
    const int s0  = cu[seq];
    const int L   = cu[seq + 1] - s0;
    const int q0  = blockIdx.x * 64;
    if (q0 >= L) return;

    const int tid = threadIdx.x;
    const int tx = tid & 15, ty = tid >> 4;
    const int orow = tid >> 2, og = tid & 3;
    const float scale = 0.11785113019775793f; // 72^-0.5

    const float* Qg = g_q + (size_t)h * T * HD;
    const float* Kg = g_k + (size_t)h * T * HD;
    const float* Vg = g_v + (size_t)h * T * HD;

    for (int t = tid; t < 64 * 18; t += 256) {
        const int r = t / 18, c = (t - r * 18) * 4;
        float4 v = make_float4(0.f, 0.f, 0.f, 0.f);
        if (q0 + r < L) v = *(const float4*)(Qg + (size_t)(s0 + q0 + r) * HD + c);
        v.x *= scale; v.y *= scale; v.z *= scale; v.w *= scale;
        *(float4*)(Qs + r * 76 + c) = v;
    }
    if (tid < 128) {
        const int r = tid >> 1, c = 72 + (tid & 1) * 4;
        *(float4*)(Vs + r * 80 + c) = make_float4(0.f, 0.f, 0.f, 0.f);
    }

    float m_run[4], l_run[4];
#pragma unroll
    for (int i = 0; i < 4; i++) { m_run[i] = -1e30f; l_run[i] = 0.f; }
    float oacc[20];
#pragma unroll
    for (int c = 0; c < 20; c++) oacc[c] = 0.f;

    const int nkt = (L + 63) >> 6;
    for (int kt = 0; kt < nkt; kt++) {
        const int k0 = kt * 64;
        __syncthreads();

        for (int t = tid; t < 64 * 18; t += 256) {
            const int r = t / 18, c = (t - r * 18) * 4;
            float4 kv = make_float4(0.f, 0.f, 0.f, 0.f);
            float4 vv = kv;
            if (k0 + r < L) {
                const size_t off = (size_t)(s0 + k0 + r) * HD + c;
                kv = *(const float4*)(Kg + off);
                vv = *(const float4*)(Vg + off);
            }
            *(float4*)(Ks + r * 76 + c) = kv;
            *(float4*)(Vs + r * 80 + c) = vv;
        }
        __syncthreads();

        float s[4][4];
#pragma unroll
        for (int i = 0; i < 4; i++)
#pragma unroll
            for (int j = 0; j < 4; j++) s[i][j] = 0.f;

        const float4* Q4 = (const float4*)Qs;  // stride 19
        const float4* K4 = (const float4*)Ks;  // stride 19
#pragma unroll 3
        for (int d4 = 0; d4 < 18; d4++) {
            float4 a[4], b[4];
#pragma unroll
            for (int i = 0; i < 4; i++) a[i] = Q4[(ty * 4 + i) * 19 + d4];
#pragma unroll
            for (int j = 0; j < 4; j++) b[j] = K4[(tx * 4 + j) * 19 + d4];
#pragma unroll
            for (int i = 0; i < 4; i++)
#pragma unroll
                for (int j = 0; j < 4; j++) {
                    s[i][j] += a[i].x * b[j].x;
                    s[i][j] += a[i].y * b[j].y;
                    s[i][j] += a[i].z * b[j].z;
                    s[i][j] += a[i].w * b[j].w;
                }
        }

#pragma unroll
        for (int i = 0; i < 4; i++) {
            float mloc = -1e30f;
#pragma unroll
            for (int j = 0; j < 4; j++) {
                if (k0 + tx * 4 + j >= L) s[i][j] = -1e30f;
                mloc = fmaxf(mloc, s[i][j]);
            }
#pragma unroll
            for (int off = 8; off > 0; off >>= 1)
                mloc = fmaxf(mloc, __shfl_xor_sync(0xffffffffu, mloc, off));
            const float mn = fmaxf(m_run[i], mloc);
            const float alpha = __expf(m_run[i] - mn);
            float ls = 0.f;
#pragma unroll
            for (int j = 0; j < 4; j++) {
                const float p = __expf(s[i][j] - mn);
                s[i][j] = p;
                ls += p;
            }
#pragma unroll
            for (int off = 8; off > 0; off >>= 1)
                ls += __shfl_xor_sync(0xffffffffu, ls, off);
            l_run[i] = l_run[i] * alpha + ls;
            m_run[i] = mn;
            if (tx == 0) rAlpha[ty * 4 + i] = alpha;
            *(float4*)&Ps[(ty * 4 + i) * 68 + tx * 4] = *(float4*)&s[i][0];
        }
        __syncthreads();

        {
            const float alpha = rAlpha[orow];
#pragma unroll
            for (int c = 0; c < 20; c++) oacc[c] *= alpha;
            const float* prow = Ps + orow * 68;
            const float4* V4 = (const float4*)Vs;   // stride 20
            const int cb = og * 5;
#pragma unroll 2
            for (int j = 0; j < 64; j++) {
                const float p = prow[j];
                const float4 v0 = V4[j * 20 + cb + 0];
                const float4 v1 = V4[j * 20 + cb + 1];
                const float4 v2 = V4[j * 20 + cb + 2];
                const float4 v3 = V4[j * 20 + cb + 3];
                const float4 v4 = V4[j * 20 + cb + 4];
                oacc[0]  += p * v0.x; oacc[1]  += p * v0.y; oacc[2]  += p * v0.z; oacc[3]  += p * v0.w;
                oacc[4]  += p * v1.x; oacc[5]  += p * v1.y; oacc[6]  += p * v1.z; oacc[7]  += p * v1.w;
                oacc[8]  += p * v2.x; oacc[9]  += p * v2.y; oacc[10] += p * v2.z; oacc[11] += p * v2.w;
                oacc[12] += p * v3.x; oacc[13] += p * v3.y; oacc[14] += p * v3.z; oacc[15] += p * v3.w;
                oacc[16] += p * v4.x; oacc[17] += p * v4.y; oacc[18] += p * v4.z; oacc[19] += p * v4.w;
            }
        }
    }

    if (tx == 0) {
#pragma unroll
        for (int i = 0; i < 4; i++) rL[ty * 4 + i] = l_run[i];
    }
    __syncthreads();

    if (q0 + orow < L) {
        const float inv = 1.f / rL[orow];
        float* Og = g_o + (size_t)(s0 + q0 + orow) * EMB + h * HD + og * 20;
        const int nf4 = (og == 3) ? 3 : 5;
#pragma unroll
        for (int c4 = 0; c4 < 5; c4++) {
            if (c4 < nf4) {
                float4 v;
                v.x = oacc[c4 * 4 + 0] * inv;
                v.y = oacc[c4 * 4 + 1] * inv;
                v.z = oacc[c4 * 4 + 2] * inv;
                v.w = oacc[c4 * 4 + 3] * inv;
                *(float4*)(Og + c4 * 4) = v;
            }
        }
    }
}

// ---------------------------------------------------------------------------
extern "C" void kernel_launch(void* const* d_in, const int* in_sizes, int n_in,
                              void* d_out, int out_size)
{
    const float* x    = (const float*)d_in[0];
    const float* wqkv = (const float*)d_in[1];
    const float* bqkv = (const float*)d_in[2];
    const float* wout = (const float*)d_in[3];
    const float* bout = (const float*)d_in[4];
    const int*   cu   = (const int*)d_in[5];

    const int T = in_sizes[0] / EMB;      // 4096
    const int nseq = in_sizes[5] - 1;     // 8

    const int SMEM_GEMM = 2 * STAGEB;     // 147456 B
    cudaFuncSetAttribute(tc_gemm<0>, cudaFuncAttributeMaxDynamicSharedMemorySize, SMEM_GEMM);
    cudaFuncSetAttribute(tc_gemm<1>, cudaFuncAttributeMaxDynamicSharedMemorySize, SMEM_GEMM);

    const int SMEM_ATTN = (64 * 76 * 2 + 64 * 80 + 64 * 68 + 128) * (int)sizeof(float);
    cudaFuncSetAttribute(attn_kernel, cudaFuncAttributeMaxDynamicSharedMemorySize, SMEM_ATTN);

    dim3 blk(256);

    // 0) fp32 -> bf16 hi/lo splits for x, wqkv, wout
    {
        int n4;
        n4 = (T * EMB) / 4;
        cvt_split<0><<<(n4 + 255) / 256, 256>>>((const float4*)x, n4);
        n4 = (E3 * EMB) / 4;
        cvt_split<1><<<(n4 + 255) / 256, 256>>>((const float4*)wqkv, n4);
        n4 = (EMB * EMB) / 4;
        cvt_split<2><<<(n4 + 255) / 256, 256>>>((const float4*)wout, n4);
    }

    // 1) fused QKV projection (HMMA) + scatter to [h][t][d]
    dim3 g1(E3 / 128, T / 128);
    tc_gemm<0><<<g1, blk, SMEM_GEMM>>>(bqkv, nullptr, T, E3, EMB);

    // 2) block-diagonal varlen attention -> g_o [t][e]
    dim3 ga((T + 63) / 64, NH, nseq);
    attn_kernel<<<ga, blk, SMEM_ATTN>>>(cu, T);

    // 2b) split attention output to bf16 hi/lo
    {
        int n4 = (T * EMB) / 4;
        cvt_split<3><<<(n4 + 255) / 256, 256>>>(nullptr, n4);
    }

    // 3) output projection (HMMA) -> d_out
    dim3 g2(EMB / 128, T / 128);
    tc_gemm<1><<<g2, blk, SMEM_GEMM>>>(bout, (float*)d_out, T, EMB, EMB);
}

// round 9
// speedup vs baseline: 3.2137x; 2.1329x over previous
#include <cuda_runtime.h>
#include <cuda_bf16.h>
#include <cstdint>

#define TMAX 4096
#define EMB  1152
#define NH   16
#define HD   72
#define E3   (3 * EMB)

// ---------------- scratch (__device__ globals; allocation-free rule) -------
__device__ float g_q[(size_t)NH * TMAX * HD];
__device__ float g_k[(size_t)NH * TMAX * HD];
__device__ float g_v[(size_t)NH * TMAX * HD];
__device__ float g_o[(size_t)TMAX * EMB];

__device__ unsigned short g_xh[(size_t)TMAX * EMB];
__device__ unsigned short g_xl[(size_t)TMAX * EMB];
__device__ unsigned short g_w1h[(size_t)E3 * EMB];
__device__ unsigned short g_w1l[(size_t)E3 * EMB];
__device__ unsigned short g_w2h[(size_t)EMB * EMB];
__device__ unsigned short g_w2l[(size_t)EMB * EMB];
__device__ unsigned short g_oh[(size_t)TMAX * EMB];
__device__ unsigned short g_ol[(size_t)TMAX * EMB];

// ---------------- base-PTX helpers (NO tcgen05 — target is compute_103) ----
__device__ __forceinline__ uint32_t smem_u32(const void* p) {
    uint32_t a;
    asm("{ .reg .u64 t; cvta.to.shared.u64 t, %1; cvt.u32.u64 %0, t; }"
        : "=r"(a) : "l"(p));
    return a;
}

__device__ __forceinline__ void cp16(uint32_t dst, const void* src) {
    asm volatile("cp.async.cg.shared.global [%0], [%1], 16;"
                 :: "r"(dst), "l"(src) : "memory");
}
#define CP_COMMIT() asm volatile("cp.async.commit_group;" ::: "memory")
#define CP_WAIT0()  asm volatile("cp.async.wait_group 0;" ::: "memory")

__device__ __forceinline__ void ldm4(uint32_t addr, uint32_t& r0, uint32_t& r1,
                                     uint32_t& r2, uint32_t& r3) {
    asm volatile("ldmatrix.sync.aligned.m8n8.x4.shared.b16 {%0,%1,%2,%3}, [%4];"
                 : "=r"(r0), "=r"(r1), "=r"(r2), "=r"(r3) : "r"(addr));
}

__device__ __forceinline__ void ldm4t(uint32_t addr, uint32_t& r0, uint32_t& r1,
                                      uint32_t& r2, uint32_t& r3) {
    asm volatile("ldmatrix.sync.aligned.m8n8.x4.trans.shared.b16 {%0,%1,%2,%3}, [%4];"
                 : "=r"(r0), "=r"(r1), "=r"(r2), "=r"(r3) : "r"(addr));
}

__device__ __forceinline__ void mma_bf16(float& c0, float& c1, float& c2, float& c3,
                                         uint32_t a0, uint32_t a1, uint32_t a2, uint32_t a3,
                                         uint32_t b0, uint32_t b1) {
    asm volatile(
        "mma.sync.aligned.m16n8k16.row.col.f32.bf16.bf16.f32 "
        "{%0,%1,%2,%3}, {%4,%5,%6,%7}, {%8,%9}, {%0,%1,%2,%3};"
        : "+f"(c0), "+f"(c1), "+f"(c2), "+f"(c3)
        : "r"(a0), "r"(a1), "r"(a2), "r"(a3), "r"(b0), "r"(b1));
}

// pack (x0,x1) -> bf16x2 hi (x0 in low half), residual pair -> lo
__device__ __forceinline__ uint32_t packsplit(float x0, float x1, uint32_t& lopack) {
    uint32_t h;
    asm("cvt.rn.bf16x2.f32 %0, %1, %2;" : "=r"(h) : "f"(x1), "f"(x0));
    float r0 = x0 - __uint_as_float(h << 16);
    float r1 = x1 - __uint_as_float(h & 0xffff0000u);
    asm("cvt.rn.bf16x2.f32 %0, %1, %2;" : "=r"(lopack) : "f"(r1), "f"(r0));
    return h;
}

// ---------------------------------------------------------------------------
// fp32 -> (bf16 hi, bf16 lo) split conversion.  WHICH: 0=x, 1=wqkv, 2=wout, 3=g_o
// ---------------------------------------------------------------------------
template <int WHICH>
__global__ void cvt_split(const float4* __restrict__ srcIn, int n4)
{
    int i = blockIdx.x * blockDim.x + threadIdx.x;
    if (i >= n4) return;
    unsigned short* hi;
    unsigned short* lo;
    const float4* src = srcIn;
    if (WHICH == 0)      { hi = g_xh;  lo = g_xl;  }
    else if (WHICH == 1) { hi = g_w1h; lo = g_w1l; }
    else if (WHICH == 2) { hi = g_w2h; lo = g_w2l; }
    else                 { hi = g_oh;  lo = g_ol;  src = (const float4*)g_o; }

    float4 v = src[i];
    float f[4] = {v.x, v.y, v.z, v.w};
    unsigned short h[4], l[4];
#pragma unroll
    for (int j = 0; j < 4; j++) {
        __nv_bfloat16 hb = __float2bfloat16(f[j]);
        h[j] = __bfloat16_as_ushort(hb);
        float r = f[j] - __bfloat162float(hb);
        l[j] = __bfloat16_as_ushort(__float2bfloat16(r));
    }
    ((ushort4*)hi)[i] = make_ushort4(h[0], h[1], h[2], h[3]);
    ((ushort4*)lo)[i] = make_ushort4(l[0], l[1], l[2], l[3]);
}

// ---------------------------------------------------------------------------
// bf16-split NT GEMM via mma.sync (unchanged from R8 — passing, tensor=58%)
// ---------------------------------------------------------------------------
#define ROWB   144
#define MATB   18432
#define STAGEB 73728

template <int MODE>
__global__ __launch_bounds__(256)
void tc_gemm(const float* __restrict__ bias, float* __restrict__ C,
             int M, int N, int K)
{
    extern __shared__ char smem[];
    const uint32_t sb = smem_u32(smem);
    const int tid  = threadIdx.x;
    const int wid  = tid >> 5, lane = tid & 31;
    const int wm   = wid & 1;
    const int wn   = wid >> 1;
    const int bm = blockIdx.y * 128, bn = blockIdx.x * 128;

    const unsigned short* Ah = (MODE == 0) ? g_xh  : g_oh;
    const unsigned short* Al = (MODE == 0) ? g_xl  : g_ol;
    const unsigned short* Bh = (MODE == 0) ? g_w1h : g_w2h;
    const unsigned short* Bl = (MODE == 0) ? g_w1l : g_w2l;

    const int la_row = lane & 15;
    const int la_k   = (lane >> 4) * 8;
    const int lb_n   = (lane & 7) + ((lane >> 4) & 1) * 8;
    const int lb_k   = ((lane >> 3) & 1) * 8;

    float c[4][4][4];
#pragma unroll
    for (int i = 0; i < 4; i++)
#pragma unroll
        for (int j = 0; j < 4; j++)
#pragma unroll
            for (int r = 0; r < 4; r++) c[i][j][r] = 0.f;

    const int nc = K >> 6;

    auto issue = [&](int kc, uint32_t stBase) {
        const int c0 = kc << 6;
#pragma unroll
        for (int it = 0; it < 4; it++) {
            const int idx = it * 256 + tid;
            const int row = idx >> 3, ch = idx & 7;
            const uint32_t doff = (uint32_t)row * ROWB + ch * 16;
            cp16(stBase + 0 * MATB + doff, Ah + (size_t)(bm + row) * K + c0 + ch * 8);
            cp16(stBase + 1 * MATB + doff, Al + (size_t)(bm + row) * K + c0 + ch * 8);
            cp16(stBase + 2 * MATB + doff, Bh + (size_t)(bn + row) * K + c0 + ch * 8);
            cp16(stBase + 3 * MATB + doff, Bl + (size_t)(bn + row) * K + c0 + ch * 8);
        }
        CP_COMMIT();
    };

    issue(0, sb);

    for (int kc = 0; kc < nc; kc++) {
        CP_WAIT0();
        __syncthreads();
        if (kc + 1 < nc) issue(kc + 1, sb + ((kc + 1) & 1) * STAGEB);

        const uint32_t st  = sb + (kc & 1) * STAGEB;
        const uint32_t stAh = st;
        const uint32_t stAl = st + MATB;
        const uint32_t stBh = st + 2 * MATB;
        const uint32_t stBl = st + 3 * MATB;

#pragma unroll
        for (int ks = 0; ks < 4; ks++) {
            const int k0 = ks * 16;
            uint32_t ah[4][4], al[4][4], bh[2][4], bl[2][4];
#pragma unroll
            for (int mt = 0; mt < 4; mt++) {
                const uint32_t ra = (uint32_t)(wm * 64 + mt * 16 + la_row) * ROWB
                                  + (uint32_t)(k0 + la_k) * 2;
                ldm4(stAh + ra, ah[mt][0], ah[mt][1], ah[mt][2], ah[mt][3]);
                ldm4(stAl + ra, al[mt][0], al[mt][1], al[mt][2], al[mt][3]);
            }
#pragma unroll
            for (int np = 0; np < 2; np++) {
                const uint32_t rb = (uint32_t)(wn * 32 + np * 16 + lb_n) * ROWB
                                  + (uint32_t)(k0 + lb_k) * 2;
                ldm4(stBh + rb, bh[np][0], bh[np][1], bh[np][2], bh[np][3]);
                ldm4(stBl + rb, bl[np][0], bl[np][1], bl[np][2], bl[np][3]);
            }
#pragma unroll
            for (int mt = 0; mt < 4; mt++)
#pragma unroll
                for (int nt = 0; nt < 4; nt++) {
                    const int np = nt >> 1, jo = (nt & 1) * 2;
                    float* cc = c[mt][nt];
                    mma_bf16(cc[0], cc[1], cc[2], cc[3],
                             ah[mt][0], ah[mt][1], ah[mt][2], ah[mt][3],
                             bh[np][jo], bh[np][jo + 1]);
                    mma_bf16(cc[0], cc[1], cc[2], cc[3],
                             ah[mt][0], ah[mt][1], ah[mt][2], ah[mt][3],
                             bl[np][jo], bl[np][jo + 1]);
                    mma_bf16(cc[0], cc[1], cc[2], cc[3],
                             al[mt][0], al[mt][1], al[mt][2], al[mt][3],
                             bh[np][jo], bh[np][jo + 1]);
                }
        }
        __syncthreads();
    }

    const int gid = lane >> 2, qid = lane & 3;
#pragma unroll
    for (int mt = 0; mt < 4; mt++) {
        const int row0 = bm + wm * 64 + mt * 16 + gid;
#pragma unroll
        for (int nt = 0; nt < 4; nt++) {
            const int col = bn + wn * 32 + nt * 8 + qid * 2;
            const float bx = bias[col], by = bias[col + 1];
            float2 v0 = make_float2(c[mt][nt][0] + bx, c[mt][nt][1] + by);
            float2 v1 = make_float2(c[mt][nt][2] + bx, c[mt][nt][3] + by);
            if (MODE == 1) {
                *(float2*)&C[(size_t)row0 * N + col] = v0;
                *(float2*)&C[(size_t)(row0 + 8) * N + col] = v1;
            } else {
                const int which = col / EMB;
                const int r = col - which * EMB;
                const int h = r / HD;
                const int d = r - h * HD;
                float* dst = (which == 0) ? g_q : (which == 1) ? g_k : g_v;
                *(float2*)&dst[((size_t)h * M + row0) * HD + d] = v0;
                *(float2*)&dst[((size_t)h * M + row0 + 8) * HD + d] = v1;
            }
        }
    }
}

// ---------------------------------------------------------------------------
// HMMA flash attention with bf16 hi/lo split (3-term) for S and P*V.
// CTA: 128 threads (4 warps), 64 q-rows; warp owns 16 q-rows.
// Smem tiles: Qh/Ql/Kh/Kl/Vh/Vl, 64 rows x 88 bf16 (176 B stride, ldmatrix
// conflict-free). D padded 72->80 with zeros; V consumed via ldmatrix.trans.
// ---------------------------------------------------------------------------
#define AROWB 176           // 88 bf16 per row
#define AMATB (64 * AROWB)  // 11264 B per matrix

__global__ __launch_bounds__(128)
void attn_mma(const int* __restrict__ cu, int T)
{
    extern __shared__ char sm[];
    const uint32_t sb = smem_u32(sm);
    const uint32_t sQh = sb;
    const uint32_t sQl = sb + 1 * AMATB;
    const uint32_t sKh = sb + 2 * AMATB;
    const uint32_t sKl = sb + 3 * AMATB;
    const uint32_t sVh = sb + 4 * AMATB;
    const uint32_t sVl = sb + 5 * AMATB;

    const int seq = blockIdx.z, h = blockIdx.y;
    const int s0 = cu[seq];
    const int L  = cu[seq + 1] - s0;
    const int q0 = blockIdx.x * 64;
    if (q0 >= L) return;

    const int tid = threadIdx.x, wid = tid >> 5, lane = tid & 31;
    const int gid = lane >> 2, qid = lane & 3;
    const int la_row = lane & 15;
    const int la_k   = (lane >> 4) * 8;
    const int lb_n   = (lane & 7) + ((lane >> 4) & 1) * 8;
    const int lb_k   = ((lane >> 3) & 1) * 8;
    const float scale = 0.11785113019775793f; // 72^-0.5

    const float* Qg = g_q + (size_t)h * T * HD;
    const float* Kg = g_k + (size_t)h * T * HD;
    const float* Vg = g_v + (size_t)h * T * HD;

    // zero the d-padding columns (elements 72..87) of all 6 matrices
    for (int t = tid; t < 64 * 2 * 6; t += 128) {
        const int mat = t / 128, rr = (t >> 1) & 63, ch = t & 1;
        *(uint4*)(sm + mat * AMATB + rr * AROWB + 144 + ch * 16) =
            make_uint4(0, 0, 0, 0);
    }

    // stage Q tile (pre-scaled, hi/lo split)
    for (int t = tid; t < 64 * 18; t += 128) {
        const int r = t / 18, c = (t - r * 18) * 4;
        float4 v = make_float4(0.f, 0.f, 0.f, 0.f);
        if (q0 + r < L) v = *(const float4*)(Qg + (size_t)(s0 + q0 + r) * HD + c);
        v.x *= scale; v.y *= scale; v.z *= scale; v.w *= scale;
        uint32_t l01, l23;
        uint32_t h01 = packsplit(v.x, v.y, l01);
        uint32_t h23 = packsplit(v.z, v.w, l23);
        const uint32_t off = (uint32_t)r * AROWB + c * 2;
        *(uint2*)(sm + 0 * AMATB + off) = make_uint2(h01, h23);
        *(uint2*)(sm + 1 * AMATB + off) = make_uint2(l01, l23);
    }

    float oacc[10][4];
#pragma unroll
    for (int i = 0; i < 10; i++)
#pragma unroll
        for (int j = 0; j < 4; j++) oacc[i][j] = 0.f;
    float m0 = -1e30f, m1 = -1e30f, l0 = 0.f, l1 = 0.f;

    const int nkt = (L + 63) >> 6;
    for (int kt = 0; kt < nkt; kt++) {
        const int k0 = kt * 64;
        __syncthreads();

        // stage K/V tiles (hi/lo split; zero rows beyond L)
        for (int t = tid; t < 64 * 18; t += 128) {
            const int r = t / 18, c = (t - r * 18) * 4;
            float4 kv = make_float4(0.f, 0.f, 0.f, 0.f), vv = kv;
            if (k0 + r < L) {
                const size_t off = (size_t)(s0 + k0 + r) * HD + c;
                kv = *(const float4*)(Kg + off);
                vv = *(const float4*)(Vg + off);
            }
            const uint32_t off = (uint32_t)r * AROWB + c * 2;
            uint32_t l01, l23;
            uint32_t h01 = packsplit(kv.x, kv.y, l01);
            uint32_t h23 = packsplit(kv.z, kv.w, l23);
            *(uint2*)(sm + 2 * AMATB + off) = make_uint2(h01, h23);
            *(uint2*)(sm + 3 * AMATB + off) = make_uint2(l01, l23);
            h01 = packsplit(vv.x, vv.y, l01);
            h23 = packsplit(vv.z, vv.w, l23);
            *(uint2*)(sm + 4 * AMATB + off) = make_uint2(h01, h23);
            *(uint2*)(sm + 5 * AMATB + off) = make_uint2(l01, l23);
        }
        __syncthreads();

        // ---- S = Q K^T (3-term split) ----
        float s[8][4];
#pragma unroll
        for (int i = 0; i < 8; i++)
#pragma unroll
            for (int j = 0; j < 4; j++) s[i][j] = 0.f;

        const uint32_t qrow = (uint32_t)(wid * 16 + la_row) * AROWB;
#pragma unroll
        for (int ks = 0; ks < 5; ks++) {
            const uint32_t qc = (uint32_t)(ks * 16 + la_k) * 2;
            uint32_t qh[4], ql[4];
            ldm4(sQh + qrow + qc, qh[0], qh[1], qh[2], qh[3]);
            ldm4(sQl + qrow + qc, ql[0], ql[1], ql[2], ql[3]);
            const uint32_t kc = (uint32_t)(ks * 16 + lb_k) * 2;
#pragma unroll
            for (int nt16 = 0; nt16 < 4; nt16++) {
                const uint32_t krow = (uint32_t)(nt16 * 16 + lb_n) * AROWB;
                uint32_t kh[4], kl[4];
                ldm4(sKh + krow + kc, kh[0], kh[1], kh[2], kh[3]);
                ldm4(sKl + krow + kc, kl[0], kl[1], kl[2], kl[3]);
#pragma unroll
                for (int sub = 0; sub < 2; sub++) {
                    float* ss = s[nt16 * 2 + sub];
                    const int jo = sub * 2;
                    mma_bf16(ss[0], ss[1], ss[2], ss[3],
                             qh[0], qh[1], qh[2], qh[3], kh[jo], kh[jo + 1]);
                    mma_bf16(ss[0], ss[1], ss[2], ss[3],
                             qh[0], qh[1], qh[2], qh[3], kl[jo], kl[jo + 1]);
                    mma_bf16(ss[0], ss[1], ss[2], ss[3],
                             ql[0], ql[1], ql[2], ql[3], kh[jo], kh[jo + 1]);
                }
            }
        }

        // ---- online softmax on fragments ----
        float mx0 = -1e30f, mx1 = -1e30f;
#pragma unroll
        for (int nt = 0; nt < 8; nt++) {
            const int col = k0 + nt * 8 + qid * 2;
            if (col >= L)     { s[nt][0] = -1e30f; s[nt][2] = -1e30f; }
            if (col + 1 >= L) { s[nt][1] = -1e30f; s[nt][3] = -1e30f; }
            mx0 = fmaxf(mx0, fmaxf(s[nt][0], s[nt][1]));
            mx1 = fmaxf(mx1, fmaxf(s[nt][2], s[nt][3]));
        }
        mx0 = fmaxf(mx0, __shfl_xor_sync(0xffffffffu, mx0, 1));
        mx0 = fmaxf(mx0, __shfl_xor_sync(0xffffffffu, mx0, 2));
        mx1 = fmaxf(mx1, __shfl_xor_sync(0xffffffffu, mx1, 1));
        mx1 = fmaxf(mx1, __shfl_xor_sync(0xffffffffu, mx1, 2));
        const float mn0 = fmaxf(m0, mx0), mn1 = fmaxf(m1, mx1);
        const float a0 = __expf(m0 - mn0), a1 = __expf(m1 - mn1);
        float ls0 = 0.f, ls1 = 0.f;
#pragma unroll
        for (int nt = 0; nt < 8; nt++) {
            s[nt][0] = __expf(s[nt][0] - mn0); ls0 += s[nt][0];
            s[nt][1] = __expf(s[nt][1] - mn0); ls0 += s[nt][1];
            s[nt][2] = __expf(s[nt][2] - mn1); ls1 += s[nt][2];
            s[nt][3] = __expf(s[nt][3] - mn1); ls1 += s[nt][3];
        }
        ls0 += __shfl_xor_sync(0xffffffffu, ls0, 1);
        ls0 += __shfl_xor_sync(0xffffffffu, ls0, 2);
        ls1 += __shfl_xor_sync(0xffffffffu, ls1, 1);
        ls1 += __shfl_xor_sync(0xffffffffu, ls1, 2);
        l0 = l0 * a0 + ls0;  l1 = l1 * a1 + ls1;
        m0 = mn0;            m1 = mn1;
#pragma unroll
        for (int i = 0; i < 10; i++) {
            oacc[i][0] *= a0; oacc[i][1] *= a0;
            oacc[i][2] *= a1; oacc[i][3] *= a1;
        }

        // ---- O += P V (3-term split; V via ldmatrix.trans) ----
#pragma unroll
        for (int kt2 = 0; kt2 < 4; kt2++) {
            float* t0 = s[kt2 * 2];
            float* t1 = s[kt2 * 2 + 1];
            uint32_t pah[4], pal[4];
            pah[0] = packsplit(t0[0], t0[1], pal[0]);
            pah[1] = packsplit(t0[2], t0[3], pal[1]);
            pah[2] = packsplit(t1[0], t1[1], pal[2]);
            pah[3] = packsplit(t1[2], t1[3], pal[3]);
            const uint32_t vrow = (uint32_t)(kt2 * 16 + la_row) * AROWB
                                + (uint32_t)((lane >> 4) & 1) * 16;
#pragma unroll
            for (int np = 0; np < 5; np++) {
                const uint32_t off = vrow + np * 32;
                uint32_t vh[4], vl[4];
                ldm4t(sVh + off, vh[0], vh[1], vh[2], vh[3]);
                ldm4t(sVl + off, vl[0], vl[1], vl[2], vl[3]);
#pragma unroll
                for (int sub = 0; sub < 2; sub++) {
                    float* o = oacc[np * 2 + sub];
                    const int jo = sub * 2;
                    mma_bf16(o[0], o[1], o[2], o[3],
                             pah[0], pah[1], pah[2], pah[3], vh[jo], vh[jo + 1]);
                    mma_bf16(o[0], o[1], o[2], o[3],
                             pah[0], pah[1], pah[2], pah[3], vl[jo], vl[jo + 1]);
                    mma_bf16(o[0], o[1], o[2], o[3],
                             pal[0], pal[1], pal[2], pal[3], vh[jo], vh[jo + 1]);
                }
            }
        }
    }

    // ---- normalize + store ----
    const float inv0 = 1.f / l0, inv1 = 1.f / l1;
    const int r0 = q0 + wid * 16 + gid;
    const int r1 = r0 + 8;
#pragma unroll
    for (int np = 0; np < 5; np++) {
#pragma unroll
        for (int sub = 0; sub < 2; sub++) {
            if (np == 4 && sub == 1) continue;
            const int col = np * 16 + sub * 8 + qid * 2;
            float* o = oacc[np * 2 + sub];
            if (r0 < L)
                *(float2*)&g_o[(size_t)(s0 + r0) * EMB + h * HD + col] =
                    make_float2(o[0] * inv0, o[1] * inv0);
            if (r1 < L)
                *(float2*)&g_o[(size_t)(s0 + r1) * EMB + h * HD + col] =
                    make_float2(o[2] * inv1, o[3] * inv1);
        }
    }
}

// ---------------------------------------------------------------------------
extern "C" void kernel_launch(void* const* d_in, const int* in_sizes, int n_in,
                              void* d_out, int out_size)
{
    const float* x    = (const float*)d_in[0];
    const float* wqkv = (const float*)d_in[1];
    const float* bqkv = (const float*)d_in[2];
    const float* wout = (const float*)d_in[3];
    const float* bout = (const float*)d_in[4];
    const int*   cu   = (const int*)d_in[5];

    const int T = in_sizes[0] / EMB;      // 4096
    const int nseq = in_sizes[5] - 1;     // 8

    const int SMEM_GEMM = 2 * STAGEB;     // 147456 B
    cudaFuncSetAttribute(tc_gemm<0>, cudaFuncAttributeMaxDynamicSharedMemorySize, SMEM_GEMM);
    cudaFuncSetAttribute(tc_gemm<1>, cudaFuncAttributeMaxDynamicSharedMemorySize, SMEM_GEMM);

    const int SMEM_ATTN = 6 * AMATB;      // 67584 B
    cudaFuncSetAttribute(attn_mma, cudaFuncAttributeMaxDynamicSharedMemorySize, SMEM_ATTN);

    // 0) fp32 -> bf16 hi/lo splits for x, wqkv, wout
    {
        int n4;
        n4 = (T * EMB) / 4;
        cvt_split<0><<<(n4 + 255) / 256, 256>>>((const float4*)x, n4);
        n4 = (E3 * EMB) / 4;
        cvt_split<1><<<(n4 + 255) / 256, 256>>>((const float4*)wqkv, n4);
        n4 = (EMB * EMB) / 4;
        cvt_split<2><<<(n4 + 255) / 256, 256>>>((const float4*)wout, n4);
    }

    // 1) fused QKV projection (HMMA) + scatter to [h][t][d]
    dim3 g1(E3 / 128, T / 128);
    tc_gemm<0><<<g1, dim3(256), SMEM_GEMM>>>(bqkv, nullptr, T, E3, EMB);

    // 2) block-diagonal varlen attention (HMMA) -> g_o [t][e]
    dim3 ga((T + 63) / 64, NH, nseq);
    attn_mma<<<ga, dim3(128), SMEM_ATTN>>>(cu, T);

    // 2b) split attention output to bf16 hi/lo
    {
        int n4 = (T * EMB) / 4;
        cvt_split<3><<<(n4 + 255) / 256, 256>>>(nullptr, n4);
    }

    // 3) output projection (HMMA) -> d_out
    dim3 g2(EMB / 128, T / 128);
    tc_gemm<1><<<g2, dim3(256), SMEM_GEMM>>>(bout, (float*)d_out, T, EMB, EMB);
}

// round 10
// speedup vs baseline: 3.2938x; 1.0249x over previous
#include <cuda_runtime.h>
#include <cuda_bf16.h>
#include <cstdint>

#define TMAX 4096
#define EMB  1152
#define NH   16
#define HD   72
#define E3   (3 * EMB)

// ---------------- scratch (__device__ globals; allocation-free rule) -------
__device__ float g_q[(size_t)NH * TMAX * HD];
__device__ float g_k[(size_t)NH * TMAX * HD];
__device__ float g_v[(size_t)NH * TMAX * HD];

__device__ unsigned short g_xh[(size_t)TMAX * EMB];
__device__ unsigned short g_xl[(size_t)TMAX * EMB];
__device__ unsigned short g_w1h[(size_t)E3 * EMB];
__device__ unsigned short g_w1l[(size_t)E3 * EMB];
__device__ unsigned short g_w2h[(size_t)EMB * EMB];
__device__ unsigned short g_w2l[(size_t)EMB * EMB];
__device__ unsigned short g_oh[(size_t)TMAX * EMB];
__device__ unsigned short g_ol[(size_t)TMAX * EMB];

// ---------------- base-PTX helpers (NO tcgen05 — target is compute_103) ----
__device__ __forceinline__ uint32_t smem_u32(const void* p) {
    uint32_t a;
    asm("{ .reg .u64 t; cvta.to.shared.u64 t, %1; cvt.u32.u64 %0, t; }"
        : "=r"(a) : "l"(p));
    return a;
}

__device__ __forceinline__ void cp16(uint32_t dst, const void* src) {
    asm volatile("cp.async.cg.shared.global [%0], [%1], 16;"
                 :: "r"(dst), "l"(src) : "memory");
}
#define CP_COMMIT() asm volatile("cp.async.commit_group;" ::: "memory")
#define CP_WAIT0()  asm volatile("cp.async.wait_group 0;" ::: "memory")

__device__ __forceinline__ void ldm4(uint32_t addr, uint32_t& r0, uint32_t& r1,
                                     uint32_t& r2, uint32_t& r3) {
    asm volatile("ldmatrix.sync.aligned.m8n8.x4.shared.b16 {%0,%1,%2,%3}, [%4];"
                 : "=r"(r0), "=r"(r1), "=r"(r2), "=r"(r3) : "r"(addr));
}

__device__ __forceinline__ void ldm4t(uint32_t addr, uint32_t& r0, uint32_t& r1,
                                      uint32_t& r2, uint32_t& r3) {
    asm volatile("ldmatrix.sync.aligned.m8n8.x4.trans.shared.b16 {%0,%1,%2,%3}, [%4];"
                 : "=r"(r0), "=r"(r1), "=r"(r2), "=r"(r3) : "r"(addr));
}

__device__ __forceinline__ void mma_bf16(float& c0, float& c1, float& c2, float& c3,
                                         uint32_t a0, uint32_t a1, uint32_t a2, uint32_t a3,
                                         uint32_t b0, uint32_t b1) {
    asm volatile(
        "mma.sync.aligned.m16n8k16.row.col.f32.bf16.bf16.f32 "
        "{%0,%1,%2,%3}, {%4,%5,%6,%7}, {%8,%9}, {%0,%1,%2,%3};"
        : "+f"(c0), "+f"(c1), "+f"(c2), "+f"(c3)
        : "r"(a0), "r"(a1), "r"(a2), "r"(a3), "r"(b0), "r"(b1));
}

// pack (x0,x1) -> bf16x2 hi (x0 in low half), residual pair -> lo
__device__ __forceinline__ uint32_t packsplit(float x0, float x1, uint32_t& lopack) {
    uint32_t h;
    asm("cvt.rn.bf16x2.f32 %0, %1, %2;" : "=r"(h) : "f"(x1), "f"(x0));
    float r0 = x0 - __uint_as_float(h << 16);
    float r1 = x1 - __uint_as_float(h & 0xffff0000u);
    asm("cvt.rn.bf16x2.f32 %0, %1, %2;" : "=r"(lopack) : "f"(r1), "f"(r0));
    return h;
}

// ---------------------------------------------------------------------------
// fused fp32 -> (bf16 hi, bf16 lo) splits for x, wqkv, wout in ONE launch
// ---------------------------------------------------------------------------
#define N4_X  ((TMAX * EMB) / 4)
#define N4_W1 ((E3 * EMB) / 4)
#define N4_W2 ((EMB * EMB) / 4)

__global__ void cvt_all(const float4* __restrict__ x,
                        const float4* __restrict__ w1,
                        const float4* __restrict__ w2)
{
    int i = blockIdx.x * blockDim.x + threadIdx.x;
    const float4* src;
    unsigned short *hi, *lo;
    int j;
    if (i < N4_X)                { src = x;  hi = g_xh;  lo = g_xl;  j = i; }
    else if (i < N4_X + N4_W1)   { src = w1; hi = g_w1h; lo = g_w1l; j = i - N4_X; }
    else if (i < N4_X + N4_W1 + N4_W2) { src = w2; hi = g_w2h; lo = g_w2l; j = i - N4_X - N4_W1; }
    else return;

    float4 v = src[j];
    float f[4] = {v.x, v.y, v.z, v.w};
    unsigned short h[4], l[4];
#pragma unroll
    for (int t = 0; t < 4; t++) {
        __nv_bfloat16 hb = __float2bfloat16(f[t]);
        h[t] = __bfloat16_as_ushort(hb);
        float r = f[t] - __bfloat162float(hb);
        l[t] = __bfloat16_as_ushort(__float2bfloat16(r));
    }
    ((ushort4*)hi)[j] = make_ushort4(h[0], h[1], h[2], h[3]);
    ((ushort4*)lo)[j] = make_ushort4(l[0], l[1], l[2], l[3]);
}

// ---------------------------------------------------------------------------
// bf16-split NT GEMM via mma.sync.  K chunked by 32 (stage 40KB, x2 = 80KB)
// so 2 CTAs/SM fit -> 4 warps/SMSP for latency hiding.
// MODE 0: A=x(hi/lo), B=wqkv(hi/lo), epilogue scatters Q/K/V [h][t][d]
// MODE 1: A=g_oh/g_ol, B=wout(hi/lo), epilogue stores C row-major
// ---------------------------------------------------------------------------
#define ROWB   80            // 32 bf16 = 64B, padded to 80B (conflict-free)
#define MATB   (128 * ROWB)  // 10240
#define STAGEB (4 * MATB)    // 40960

template <int MODE>
__global__ __launch_bounds__(256, 2)
void tc_gemm(const float* __restrict__ bias, float* __restrict__ C,
             int M, int N, int K)
{
    extern __shared__ char smem[];
    const uint32_t sb = smem_u32(smem);
    const int tid  = threadIdx.x;
    const int wid  = tid >> 5, lane = tid & 31;
    const int wm   = wid & 1;        // 64-row half
    const int wn   = wid >> 1;       // 32-col quarter
    const int bm = blockIdx.y * 128, bn = blockIdx.x * 128;

    const unsigned short* Ah = (MODE == 0) ? g_xh  : g_oh;
    const unsigned short* Al = (MODE == 0) ? g_xl  : g_ol;
    const unsigned short* Bh = (MODE == 0) ? g_w1h : g_w2h;
    const unsigned short* Bl = (MODE == 0) ? g_w1l : g_w2l;

    const int la_row = lane & 15;
    const int la_k   = (lane >> 4) * 8;
    const int lb_n   = (lane & 7) + ((lane >> 4) & 1) * 8;
    const int lb_k   = ((lane >> 3) & 1) * 8;

    float c[4][4][4];
#pragma unroll
    for (int i = 0; i < 4; i++)
#pragma unroll
        for (int j = 0; j < 4; j++)
#pragma unroll
            for (int r = 0; r < 4; r++) c[i][j][r] = 0.f;

    const int nc = K >> 5;   // 32-K chunks

    auto issue = [&](int kc, uint32_t stBase) {
        const int c0 = kc << 5;
#pragma unroll
        for (int it = 0; it < 2; it++) {
            const int idx = it * 256 + tid;      // 0..511
            const int row = idx >> 2, ch = idx & 3;
            const uint32_t doff = (uint32_t)row * ROWB + ch * 16;
            const size_t soff = (size_t)row * K + c0 + ch * 8;
            cp16(stBase + 0 * MATB + doff, Ah + (size_t)bm * K + soff);
            cp16(stBase + 1 * MATB + doff, Al + (size_t)bm * K + soff);
            cp16(stBase + 2 * MATB + doff, Bh + (size_t)bn * K + soff);
            cp16(stBase + 3 * MATB + doff, Bl + (size_t)bn * K + soff);
        }
        CP_COMMIT();
    };

    issue(0, sb);

    for (int kc = 0; kc < nc; kc++) {
        CP_WAIT0();
        __syncthreads();
        if (kc + 1 < nc) issue(kc + 1, sb + ((kc + 1) & 1) * STAGEB);

        const uint32_t st   = sb + (kc & 1) * STAGEB;
        const uint32_t stAh = st;
        const uint32_t stAl = st + MATB;
        const uint32_t stBh = st + 2 * MATB;
        const uint32_t stBl = st + 3 * MATB;

#pragma unroll
        for (int ks = 0; ks < 2; ks++) {
            const int k0 = ks * 16;
            uint32_t ah[4][4], al[4][4], bh[2][4], bl[2][4];
#pragma unroll
            for (int mt = 0; mt < 4; mt++) {
                const uint32_t ra = (uint32_t)(wm * 64 + mt * 16 + la_row) * ROWB
                                  + (uint32_t)(k0 + la_k) * 2;
                ldm4(stAh + ra, ah[mt][0], ah[mt][1], ah[mt][2], ah[mt][3]);
                ldm4(stAl + ra, al[mt][0], al[mt][1], al[mt][2], al[mt][3]);
            }
#pragma unroll
            for (int np = 0; np < 2; np++) {
                const uint32_t rb = (uint32_t)(wn * 32 + np * 16 + lb_n) * ROWB
                                  + (uint32_t)(k0 + lb_k) * 2;
                ldm4(stBh + rb, bh[np][0], bh[np][1], bh[np][2], bh[np][3]);
                ldm4(stBl + rb, bl[np][0], bl[np][1], bl[np][2], bl[np][3]);
            }
#pragma unroll
            for (int mt = 0; mt < 4; mt++)
#pragma unroll
                for (int nt = 0; nt < 4; nt++) {
                    const int np = nt >> 1, jo = (nt & 1) * 2;
                    float* cc = c[mt][nt];
                    mma_bf16(cc[0], cc[1], cc[2], cc[3],
                             ah[mt][0], ah[mt][1], ah[mt][2], ah[mt][3],
                             bh[np][jo], bh[np][jo + 1]);
                    mma_bf16(cc[0], cc[1], cc[2], cc[3],
                             ah[mt][0], ah[mt][1], ah[mt][2], ah[mt][3],
                             bl[np][jo], bl[np][jo + 1]);
                    mma_bf16(cc[0], cc[1], cc[2], cc[3],
                             al[mt][0], al[mt][1], al[mt][2], al[mt][3],
                             bh[np][jo], bh[np][jo + 1]);
                }
        }
        __syncthreads();
    }

    const int gid = lane >> 2, qid = lane & 3;
#pragma unroll
    for (int mt = 0; mt < 4; mt++) {
        const int row0 = bm + wm * 64 + mt * 16 + gid;
#pragma unroll
        for (int nt = 0; nt < 4; nt++) {
            const int col = bn + wn * 32 + nt * 8 + qid * 2;
            const float bx = bias[col], by = bias[col + 1];
            float2 v0 = make_float2(c[mt][nt][0] + bx, c[mt][nt][1] + by);
            float2 v1 = make_float2(c[mt][nt][2] + bx, c[mt][nt][3] + by);
            if (MODE == 1) {
                *(float2*)&C[(size_t)row0 * N + col] = v0;
                *(float2*)&C[(size_t)(row0 + 8) * N + col] = v1;
            } else {
                const int which = col / EMB;
                const int r = col - which * EMB;
                const int h = r / HD;
                const int d = r - h * HD;
                float* dst = (which == 0) ? g_q : (which == 1) ? g_k : g_v;
                *(float2*)&dst[((size_t)h * M + row0) * HD + d] = v0;
                *(float2*)&dst[((size_t)h * M + row0 + 8) * HD + d] = v1;
            }
        }
    }
}

// ---------------------------------------------------------------------------
// HMMA flash attention, bf16 hi/lo split (3-term) for S and P*V.
// Epilogue now writes bf16 hi/lo directly to g_oh/g_ol (feeds tc_gemm<1>).
// ---------------------------------------------------------------------------
#define AROWB 176           // 88 bf16 per row
#define AMATB (64 * AROWB)  // 11264 B per matrix

__global__ __launch_bounds__(128)
void attn_mma(const int* __restrict__ cu, int T)
{
    extern __shared__ char sm[];
    const uint32_t sb = smem_u32(sm);
    const uint32_t sQh = sb;
    const uint32_t sQl = sb + 1 * AMATB;
    const uint32_t sKh = sb + 2 * AMATB;
    const uint32_t sKl = sb + 3 * AMATB;
    const uint32_t sVh = sb + 4 * AMATB;
    const uint32_t sVl = sb + 5 * AMATB;

    const int seq = blockIdx.z, h = blockIdx.y;
    const int s0 = cu[seq];
    const int L  = cu[seq + 1] - s0;
    const int q0 = blockIdx.x * 64;
    if (q0 >= L) return;

    const int tid = threadIdx.x, wid = tid >> 5, lane = tid & 31;
    const int gid = lane >> 2, qid = lane & 3;
    const int la_row = lane & 15;
    const int la_k   = (lane >> 4) * 8;
    const int lb_n   = (lane & 7) + ((lane >> 4) & 1) * 8;
    const int lb_k   = ((lane >> 3) & 1) * 8;
    const float scale = 0.11785113019775793f; // 72^-0.5

    const float* Qg = g_q + (size_t)h * T * HD;
    const float* Kg = g_k + (size_t)h * T * HD;
    const float* Vg = g_v + (size_t)h * T * HD;

    for (int t = tid; t < 64 * 2 * 6; t += 128) {
        const int mat = t / 128, rr = (t >> 1) & 63, ch = t & 1;
        *(uint4*)(sm + mat * AMATB + rr * AROWB + 144 + ch * 16) =
            make_uint4(0, 0, 0, 0);
    }

    for (int t = tid; t < 64 * 18; t += 128) {
        const int r = t / 18, c = (t - r * 18) * 4;
        float4 v = make_float4(0.f, 0.f, 0.f, 0.f);
        if (q0 + r < L) v = *(const float4*)(Qg + (size_t)(s0 + q0 + r) * HD + c);
        v.x *= scale; v.y *= scale; v.z *= scale; v.w *= scale;
        uint32_t l01, l23;
        uint32_t h01 = packsplit(v.x, v.y, l01);
        uint32_t h23 = packsplit(v.z, v.w, l23);
        const uint32_t off = (uint32_t)r * AROWB + c * 2;
        *(uint2*)(sm + 0 * AMATB + off) = make_uint2(h01, h23);
        *(uint2*)(sm + 1 * AMATB + off) = make_uint2(l01, l23);
    }

    float oacc[10][4];
#pragma unroll
    for (int i = 0; i < 10; i++)
#pragma unroll
        for (int j = 0; j < 4; j++) oacc[i][j] = 0.f;
    float m0 = -1e30f, m1 = -1e30f, l0 = 0.f, l1 = 0.f;

    const int nkt = (L + 63) >> 6;
    for (int kt = 0; kt < nkt; kt++) {
        const int k0 = kt * 64;
        __syncthreads();

        for (int t = tid; t < 64 * 18; t += 128) {
            const int r = t / 18, c = (t - r * 18) * 4;
            float4 kv = make_float4(0.f, 0.f, 0.f, 0.f), vv = kv;
            if (k0 + r < L) {
                const size_t off = (size_t)(s0 + k0 + r) * HD + c;
                kv = *(const float4*)(Kg + off);
                vv = *(const float4*)(Vg + off);
            }
            const uint32_t off = (uint32_t)r * AROWB + c * 2;
            uint32_t l01, l23;
            uint32_t h01 = packsplit(kv.x, kv.y, l01);
            uint32_t h23 = packsplit(kv.z, kv.w, l23);
            *(uint2*)(sm + 2 * AMATB + off) = make_uint2(h01, h23);
            *(uint2*)(sm + 3 * AMATB + off) = make_uint2(l01, l23);
            h01 = packsplit(vv.x, vv.y, l01);
            h23 = packsplit(vv.z, vv.w, l23);
            *(uint2*)(sm + 4 * AMATB + off) = make_uint2(h01, h23);
            *(uint2*)(sm + 5 * AMATB + off) = make_uint2(l01, l23);
        }
        __syncthreads();

        float s[8][4];
#pragma unroll
        for (int i = 0; i < 8; i++)
#pragma unroll
            for (int j = 0; j < 4; j++) s[i][j] = 0.f;

        const uint32_t qrow = (uint32_t)(wid * 16 + la_row) * AROWB;
#pragma unroll
        for (int ks = 0; ks < 5; ks++) {
            const uint32_t qc = (uint32_t)(ks * 16 + la_k) * 2;
            uint32_t qh[4], ql[4];
            ldm4(sQh + qrow + qc, qh[0], qh[1], qh[2], qh[3]);
            ldm4(sQl + qrow + qc, ql[0], ql[1], ql[2], ql[3]);
            const uint32_t kc = (uint32_t)(ks * 16 + lb_k) * 2;
#pragma unroll
            for (int nt16 = 0; nt16 < 4; nt16++) {
                const uint32_t krow = (uint32_t)(nt16 * 16 + lb_n) * AROWB;
                uint32_t kh[4], kl[4];
                ldm4(sKh + krow + kc, kh[0], kh[1], kh[2], kh[3]);
                ldm4(sKl + krow + kc, kl[0], kl[1], kl[2], kl[3]);
#pragma unroll
                for (int sub = 0; sub < 2; sub++) {
                    float* ss = s[nt16 * 2 + sub];
                    const int jo = sub * 2;
                    mma_bf16(ss[0], ss[1], ss[2], ss[3],
                             qh[0], qh[1], qh[2], qh[3], kh[jo], kh[jo + 1]);
                    mma_bf16(ss[0], ss[1], ss[2], ss[3],
                             qh[0], qh[1], qh[2], qh[3], kl[jo], kl[jo + 1]);
                    mma_bf16(ss[0], ss[1], ss[2], ss[3],
                             ql[0], ql[1], ql[2], ql[3], kh[jo], kh[jo + 1]);
                }
            }
        }

        float mx0 = -1e30f, mx1 = -1e30f;
#pragma unroll
        for (int nt = 0; nt < 8; nt++) {
            const int col = k0 + nt * 8 + qid * 2;
            if (col >= L)     { s[nt][0] = -1e30f; s[nt][2] = -1e30f; }
            if (col + 1 >= L) { s[nt][1] = -1e30f; s[nt][3] = -1e30f; }
            mx0 = fmaxf(mx0, fmaxf(s[nt][0], s[nt][1]));
            mx1 = fmaxf(mx1, fmaxf(s[nt][2], s[nt][3]));
        }
        mx0 = fmaxf(mx0, __shfl_xor_sync(0xffffffffu, mx0, 1));
        mx0 = fmaxf(mx0, __shfl_xor_sync(0xffffffffu, mx0, 2));
        mx1 = fmaxf(mx1, __shfl_xor_sync(0xffffffffu, mx1, 1));
        mx1 = fmaxf(mx1, __shfl_xor_sync(0xffffffffu, mx1, 2));
        const float mn0 = fmaxf(m0, mx0), mn1 = fmaxf(m1, mx1);
        const float a0 = __expf(m0 - mn0), a1 = __expf(m1 - mn1);
        float ls0 = 0.f, ls1 = 0.f;
#pragma unroll
        for (int nt = 0; nt < 8; nt++) {
            s[nt][0] = __expf(s[nt][0] - mn0); ls0 += s[nt][0];
            s[nt][1] = __expf(s[nt][1] - mn0); ls0 += s[nt][1];
            s[nt][2] = __expf(s[nt][2] - mn1); ls1 += s[nt][2];
            s[nt][3] = __expf(s[nt][3] - mn1); ls1 += s[nt][3];
        }
        ls0 += __shfl_xor_sync(0xffffffffu, ls0, 1);
        ls0 += __shfl_xor_sync(0xffffffffu, ls0, 2);
        ls1 += __shfl_xor_sync(0xffffffffu, ls1, 1);
        ls1 += __shfl_xor_sync(0xffffffffu, ls1, 2);
        l0 = l0 * a0 + ls0;  l1 = l1 * a1 + ls1;
        m0 = mn0;            m1 = mn1;
#pragma unroll
        for (int i = 0; i < 10; i++) {
            oacc[i][0] *= a0; oacc[i][1] *= a0;
            oacc[i][2] *= a1; oacc[i][3] *= a1;
        }

#pragma unroll
        for (int kt2 = 0; kt2 < 4; kt2++) {
            float* t0 = s[kt2 * 2];
            float* t1 = s[kt2 * 2 + 1];
            uint32_t pah[4], pal[4];
            pah[0] = packsplit(t0[0], t0[1], pal[0]);
            pah[1] = packsplit(t0[2], t0[3], pal[1]);
            pah[2] = packsplit(t1[0], t1[1], pal[2]);
            pah[3] = packsplit(t1[2], t1[3], pal[3]);
            const uint32_t vrow = (uint32_t)(kt2 * 16 + la_row) * AROWB
                                + (uint32_t)((lane >> 4) & 1) * 16;
#pragma unroll
            for (int np = 0; np < 5; np++) {
                const uint32_t off = vrow + np * 32;
                uint32_t vh[4], vl[4];
                ldm4t(sVh + off, vh[0], vh[1], vh[2], vh[3]);
                ldm4t(sVl + off, vl[0], vl[1], vl[2], vl[3]);
#pragma unroll
                for (int sub = 0; sub < 2; sub++) {
                    float* o = oacc[np * 2 + sub];
                    const int jo = sub * 2;
                    mma_bf16(o[0], o[1], o[2], o[3],
                             pah[0], pah[1], pah[2], pah[3], vh[jo], vh[jo + 1]);
                    mma_bf16(o[0], o[1], o[2], o[3],
                             pah[0], pah[1], pah[2], pah[3], vl[jo], vl[jo + 1]);
                    mma_bf16(o[0], o[1], o[2], o[3],
                             pal[0], pal[1], pal[2], pal[3], vh[jo], vh[jo + 1]);
                }
            }
        }
    }

    // ---- normalize + store bf16 hi/lo directly (feeds tc_gemm<1>) ----
    const float inv0 = 1.f / l0, inv1 = 1.f / l1;
    const int r0 = q0 + wid * 16 + gid;
    const int r1 = r0 + 8;
#pragma unroll
    for (int np = 0; np < 5; np++) {
#pragma unroll
        for (int sub = 0; sub < 2; sub++) {
            if (np == 4 && sub == 1) continue;
            const int col = np * 16 + sub * 8 + qid * 2;
            float* o = oacc[np * 2 + sub];
            if (r0 < L) {
                const size_t idx = (size_t)(s0 + r0) * EMB + h * HD + col;
                uint32_t lo, hi = packsplit(o[0] * inv0, o[1] * inv0, lo);
                *(uint32_t*)&g_oh[idx] = hi;
                *(uint32_t*)&g_ol[idx] = lo;
            }
            if (r1 < L) {
                const size_t idx = (size_t)(s0 + r1) * EMB + h * HD + col;
                uint32_t lo, hi = packsplit(o[2] * inv1, o[3] * inv1, lo);
                *(uint32_t*)&g_oh[idx] = hi;
                *(uint32_t*)&g_ol[idx] = lo;
            }
        }
    }
}

// ---------------------------------------------------------------------------
extern "C" void kernel_launch(void* const* d_in, const int* in_sizes, int n_in,
                              void* d_out, int out_size)
{
    const float* x    = (const float*)d_in[0];
    const float* wqkv = (const float*)d_in[1];
    const float* bqkv = (const float*)d_in[2];
    const float* wout = (const float*)d_in[3];
    const float* bout = (const float*)d_in[4];
    const int*   cu   = (const int*)d_in[5];

    const int T = in_sizes[0] / EMB;      // 4096
    const int nseq = in_sizes[5] - 1;     // 8

    const int SMEM_GEMM = 2 * STAGEB;     // 81920 B -> 2 CTAs/SM
    cudaFuncSetAttribute(tc_gemm<0>, cudaFuncAttributeMaxDynamicSharedMemorySize, SMEM_GEMM);
    cudaFuncSetAttribute(tc_gemm<1>, cudaFuncAttributeMaxDynamicSharedMemorySize, SMEM_GEMM);

    const int SMEM_ATTN = 6 * AMATB;      // 67584 B
    cudaFuncSetAttribute(attn_mma, cudaFuncAttributeMaxDynamicSharedMemorySize, SMEM_ATTN);

    // 0) fused fp32 -> bf16 hi/lo splits (single launch)
    {
        const int ntot = N4_X + N4_W1 + N4_W2;
        cvt_all<<<(ntot + 255) / 256, 256>>>((const float4*)x,
                                             (const float4*)wqkv,
                                             (const float4*)wout);
    }

    // 1) fused QKV projection (HMMA) + scatter to [h][t][d]
    dim3 g1(E3 / 128, T / 128);
    tc_gemm<0><<<g1, dim3(256), SMEM_GEMM>>>(bqkv, nullptr, T, E3, EMB);

    // 2) block-diagonal varlen attention (HMMA) -> g_oh/g_ol bf16 split
    dim3 ga((T + 63) / 64, NH, nseq);
    attn_mma<<<ga, dim3(128), SMEM_ATTN>>>(cu, T);

    // 3) output projection (HMMA) -> d_out
    dim3 g2(EMB / 128, T / 128);
    tc_gemm<1><<<g2, dim3(256), SMEM_GEMM>>>(bout, (float*)d_out, T, EMB, EMB);
}

// round 11
// speedup vs baseline: 3.2986x; 1.0015x over previous
#include <cuda_runtime.h>
#include <cuda_bf16.h>
#include <cstdint>

#define TMAX 4096
#define EMB  1152
#define NH   16
#define HD   72
#define E3   (3 * EMB)

// ---------------- scratch (__device__ globals; allocation-free rule) -------
__device__ unsigned short g_qh[(size_t)NH * TMAX * HD];
__device__ unsigned short g_ql[(size_t)NH * TMAX * HD];
__device__ unsigned short g_kh[(size_t)NH * TMAX * HD];
__device__ unsigned short g_kl[(size_t)NH * TMAX * HD];
__device__ unsigned short g_vh[(size_t)NH * TMAX * HD];
__device__ unsigned short g_vl[(size_t)NH * TMAX * HD];

__device__ unsigned short g_xh[(size_t)TMAX * EMB];
__device__ unsigned short g_xl[(size_t)TMAX * EMB];
__device__ unsigned short g_w1h[(size_t)E3 * EMB];
__device__ unsigned short g_w1l[(size_t)E3 * EMB];
__device__ unsigned short g_w2h[(size_t)EMB * EMB];
__device__ unsigned short g_w2l[(size_t)EMB * EMB];
__device__ unsigned short g_oh[(size_t)TMAX * EMB];
__device__ unsigned short g_ol[(size_t)TMAX * EMB];

// ---------------- base-PTX helpers (NO tcgen05 — target is compute_103) ----
__device__ __forceinline__ uint32_t smem_u32(const void* p) {
    uint32_t a;
    asm("{ .reg .u64 t; cvta.to.shared.u64 t, %1; cvt.u32.u64 %0, t; }"
        : "=r"(a) : "l"(p));
    return a;
}

__device__ __forceinline__ void cp16(uint32_t dst, const void* src) {
    asm volatile("cp.async.cg.shared.global [%0], [%1], 16;"
                 :: "r"(dst), "l"(src) : "memory");
}
#define CP_COMMIT() asm volatile("cp.async.commit_group;" ::: "memory")
#define CP_WAIT0()  asm volatile("cp.async.wait_group 0;" ::: "memory")

__device__ __forceinline__ void ldm4(uint32_t addr, uint32_t& r0, uint32_t& r1,
                                     uint32_t& r2, uint32_t& r3) {
    asm volatile("ldmatrix.sync.aligned.m8n8.x4.shared.b16 {%0,%1,%2,%3}, [%4];"
                 : "=r"(r0), "=r"(r1), "=r"(r2), "=r"(r3) : "r"(addr));
}

__device__ __forceinline__ void ldm4t(uint32_t addr, uint32_t& r0, uint32_t& r1,
                                      uint32_t& r2, uint32_t& r3) {
    asm volatile("ldmatrix.sync.aligned.m8n8.x4.trans.shared.b16 {%0,%1,%2,%3}, [%4];"
                 : "=r"(r0), "=r"(r1), "=r"(r2), "=r"(r3) : "r"(addr));
}

__device__ __forceinline__ void mma_bf16(float& c0, float& c1, float& c2, float& c3,
                                         uint32_t a0, uint32_t a1, uint32_t a2, uint32_t a3,
                                         uint32_t b0, uint32_t b1) {
    asm volatile(
        "mma.sync.aligned.m16n8k16.row.col.f32.bf16.bf16.f32 "
        "{%0,%1,%2,%3}, {%4,%5,%6,%7}, {%8,%9}, {%0,%1,%2,%3};"
        : "+f"(c0), "+f"(c1), "+f"(c2), "+f"(c3)
        : "r"(a0), "r"(a1), "r"(a2), "r"(a3), "r"(b0), "r"(b1));
}

// pack (x0,x1) -> bf16x2 hi (x0 in low half), residual pair -> lo
__device__ __forceinline__ uint32_t packsplit(float x0, float x1, uint32_t& lopack) {
    uint32_t h;
    asm("cvt.rn.bf16x2.f32 %0, %1, %2;" : "=r"(h) : "f"(x1), "f"(x0));
    float r0 = x0 - __uint_as_float(h << 16);
    float r1 = x1 - __uint_as_float(h & 0xffff0000u);
    asm("cvt.rn.bf16x2.f32 %0, %1, %2;" : "=r"(lopack) : "f"(r1), "f"(r0));
    return h;
}

// ---------------------------------------------------------------------------
// fused fp32 -> (bf16 hi, bf16 lo) splits for x, wqkv, wout in ONE launch
// ---------------------------------------------------------------------------
#define N4_X  ((TMAX * EMB) / 4)
#define N4_W1 ((E3 * EMB) / 4)
#define N4_W2 ((EMB * EMB) / 4)

__global__ void cvt_all(const float4* __restrict__ x,
                        const float4* __restrict__ w1,
                        const float4* __restrict__ w2)
{
    int i = blockIdx.x * blockDim.x + threadIdx.x;
    const float4* src;
    unsigned short *hi, *lo;
    int j;
    if (i < N4_X)                { src = x;  hi = g_xh;  lo = g_xl;  j = i; }
    else if (i < N4_X + N4_W1)   { src = w1; hi = g_w1h; lo = g_w1l; j = i - N4_X; }
    else if (i < N4_X + N4_W1 + N4_W2) { src = w2; hi = g_w2h; lo = g_w2l; j = i - N4_X - N4_W1; }
    else return;

    float4 v = src[j];
    float f[4] = {v.x, v.y, v.z, v.w};
    unsigned short h[4], l[4];
#pragma unroll
    for (int t = 0; t < 4; t++) {
        __nv_bfloat16 hb = __float2bfloat16(f[t]);
        h[t] = __bfloat16_as_ushort(hb);
        float r = f[t] - __bfloat162float(hb);
        l[t] = __bfloat16_as_ushort(__float2bfloat16(r));
    }
    ((ushort4*)hi)[j] = make_ushort4(h[0], h[1], h[2], h[3]);
    ((ushort4*)lo)[j] = make_ushort4(l[0], l[1], l[2], l[3]);
}

// ---------------------------------------------------------------------------
// bf16-split NT GEMM via mma.sync.  K chunked by 32, double-buffered, 2 CTA/SM.
// MODE 0: A=x(hi/lo), B=wqkv(hi/lo), epilogue packsplits Q/K/V -> hi/lo [h][t][d]
// MODE 1: A=g_oh/g_ol, B=wout(hi/lo), epilogue stores C row-major fp32
// ---------------------------------------------------------------------------
#define ROWB   80
#define MATB   (128 * ROWB)
#define STAGEB (4 * MATB)

template <int MODE>
__global__ __launch_bounds__(256, 2)
void tc_gemm(const float* __restrict__ bias, float* __restrict__ C,
             int M, int N, int K)
{
    extern __shared__ char smem[];
    const uint32_t sb = smem_u32(smem);
    const int tid  = threadIdx.x;
    const int wid  = tid >> 5, lane = tid & 31;
    const int wm   = wid & 1;
    const int wn   = wid >> 1;
    const int bm = blockIdx.y * 128, bn = blockIdx.x * 128;

    const unsigned short* Ah = (MODE == 0) ? g_xh  : g_oh;
    const unsigned short* Al = (MODE == 0) ? g_xl  : g_ol;
    const unsigned short* Bh = (MODE == 0) ? g_w1h : g_w2h;
    const unsigned short* Bl = (MODE == 0) ? g_w1l : g_w2l;

    const int la_row = lane & 15;
    const int la_k   = (lane >> 4) * 8;
    const int lb_n   = (lane & 7) + ((lane >> 4) & 1) * 8;
    const int lb_k   = ((lane >> 3) & 1) * 8;

    float c[4][4][4];
#pragma unroll
    for (int i = 0; i < 4; i++)
#pragma unroll
        for (int j = 0; j < 4; j++)
#pragma unroll
            for (int r = 0; r < 4; r++) c[i][j][r] = 0.f;

    const int nc = K >> 5;

    auto issue = [&](int kc, uint32_t stBase) {
        const int c0 = kc << 5;
#pragma unroll
        for (int it = 0; it < 2; it++) {
            const int idx = it * 256 + tid;
            const int row = idx >> 2, ch = idx & 3;
            const uint32_t doff = (uint32_t)row * ROWB + ch * 16;
            const size_t soff = (size_t)row * K + c0 + ch * 8;
            cp16(stBase + 0 * MATB + doff, Ah + (size_t)bm * K + soff);
            cp16(stBase + 1 * MATB + doff, Al + (size_t)bm * K + soff);
            cp16(stBase + 2 * MATB + doff, Bh + (size_t)bn * K + soff);
            cp16(stBase + 3 * MATB + doff, Bl + (size_t)bn * K + soff);
        }
        CP_COMMIT();
    };

    issue(0, sb);

    for (int kc = 0; kc < nc; kc++) {
        CP_WAIT0();
        __syncthreads();
        if (kc + 1 < nc) issue(kc + 1, sb + ((kc + 1) & 1) * STAGEB);

        const uint32_t st   = sb + (kc & 1) * STAGEB;
        const uint32_t stAh = st;
        const uint32_t stAl = st + MATB;
        const uint32_t stBh = st + 2 * MATB;
        const uint32_t stBl = st + 3 * MATB;

#pragma unroll
        for (int ks = 0; ks < 2; ks++) {
            const int k0 = ks * 16;
            uint32_t ah[4][4], al[4][4], bh[2][4], bl[2][4];
#pragma unroll
            for (int mt = 0; mt < 4; mt++) {
                const uint32_t ra = (uint32_t)(wm * 64 + mt * 16 + la_row) * ROWB
                                  + (uint32_t)(k0 + la_k) * 2;
                ldm4(stAh + ra, ah[mt][0], ah[mt][1], ah[mt][2], ah[mt][3]);
                ldm4(stAl + ra, al[mt][0], al[mt][1], al[mt][2], al[mt][3]);
            }
#pragma unroll
            for (int np = 0; np < 2; np++) {
                const uint32_t rb = (uint32_t)(wn * 32 + np * 16 + lb_n) * ROWB
                                  + (uint32_t)(k0 + lb_k) * 2;
                ldm4(stBh + rb, bh[np][0], bh[np][1], bh[np][2], bh[np][3]);
                ldm4(stBl + rb, bl[np][0], bl[np][1], bl[np][2], bl[np][3]);
            }
#pragma unroll
            for (int mt = 0; mt < 4; mt++)
#pragma unroll
                for (int nt = 0; nt < 4; nt++) {
                    const int np = nt >> 1, jo = (nt & 1) * 2;
                    float* cc = c[mt][nt];
                    mma_bf16(cc[0], cc[1], cc[2], cc[3],
                             ah[mt][0], ah[mt][1], ah[mt][2], ah[mt][3],
                             bh[np][jo], bh[np][jo + 1]);
                    mma_bf16(cc[0], cc[1], cc[2], cc[3],
                             ah[mt][0], ah[mt][1], ah[mt][2], ah[mt][3],
                             bl[np][jo], bl[np][jo + 1]);
                    mma_bf16(cc[0], cc[1], cc[2], cc[3],
                             al[mt][0], al[mt][1], al[mt][2], al[mt][3],
                             bh[np][jo], bh[np][jo + 1]);
                }
        }
        // no trailing __syncthreads: next iteration's top barrier orders reuse
    }

    const int gid = lane >> 2, qid = lane & 3;
#pragma unroll
    for (int mt = 0; mt < 4; mt++) {
        const int row0 = bm + wm * 64 + mt * 16 + gid;
#pragma unroll
        for (int nt = 0; nt < 4; nt++) {
            const int col = bn + wn * 32 + nt * 8 + qid * 2;
            const float bx = bias[col], by = bias[col + 1];
            float2 v0 = make_float2(c[mt][nt][0] + bx, c[mt][nt][1] + by);
            float2 v1 = make_float2(c[mt][nt][2] + bx, c[mt][nt][3] + by);
            if (MODE == 1) {
                *(float2*)&C[(size_t)row0 * N + col] = v0;
                *(float2*)&C[(size_t)(row0 + 8) * N + col] = v1;
            } else {
                const int which = col / EMB;
                const int r = col - which * EMB;
                const int h = r / HD;
                const int d = r - h * HD;
                unsigned short* dh = (which == 0) ? g_qh : (which == 1) ? g_kh : g_vh;
                unsigned short* dl = (which == 0) ? g_ql : (which == 1) ? g_kl : g_vl;
                const size_t i0 = ((size_t)h * M + row0) * HD + d;
                const size_t i1 = ((size_t)h * M + row0 + 8) * HD + d;
                uint32_t lo0, hi0 = packsplit(v0.x, v0.y, lo0);
                uint32_t lo1, hi1 = packsplit(v1.x, v1.y, lo1);
                *(uint32_t*)&dh[i0] = hi0;  *(uint32_t*)&dl[i0] = lo0;
                *(uint32_t*)&dh[i1] = hi1;  *(uint32_t*)&dl[i1] = lo1;
            }
        }
    }
}

// ---------------------------------------------------------------------------
// HMMA flash attention, bf16 hi/lo split (3-term), cp.async staged K/V tiles
// (double-buffered; no in-kernel fp32->bf16 conversion). Q resident in smem.
// Smem: [Qh, Ql, stage0: Kh,Kl,Vh,Vl, stage1: Kh,Kl,Vh,Vl] = 10 * 11264 B.
// ---------------------------------------------------------------------------
#define AROWB 176           // 88 bf16 per row (rows hold 72 valid + 16 zero)
#define AMATB (64 * AROWB)  // 11264 B per matrix

__global__ __launch_bounds__(128)
void attn_mma(const int* __restrict__ cu, int T)
{
    extern __shared__ char sm[];
    const uint32_t sb = smem_u32(sm);

    const int seq = blockIdx.z, h = blockIdx.y;
    const int s0 = cu[seq];
    const int L  = cu[seq + 1] - s0;
    const int q0 = blockIdx.x * 64;
    if (q0 >= L) return;

    const int tid = threadIdx.x, wid = tid >> 5, lane = tid & 31;
    const int gid = lane >> 2, qid = lane & 3;
    const int la_row = lane & 15;
    const int la_k   = (lane >> 4) * 8;
    const int lb_n   = (lane & 7) + ((lane >> 4) & 1) * 8;
    const int lb_k   = ((lane >> 3) & 1) * 8;
    const float scale = 0.11785113019775793f; // 72^-0.5

    const unsigned short* QH = g_qh + (size_t)h * T * HD;
    const unsigned short* QL = g_ql + (size_t)h * T * HD;
    const unsigned short* KH = g_kh + (size_t)h * T * HD;
    const unsigned short* KL = g_kl + (size_t)h * T * HD;
    const unsigned short* VH = g_vh + (size_t)h * T * HD;
    const unsigned short* VL = g_vl + (size_t)h * T * HD;

    // zero the d-padding columns (bytes 144..175) of all 10 matrices
    for (int t = tid; t < 10 * 64 * 2; t += 128) {
        const int mat = t >> 7, rr = (t >> 1) & 63, ch = t & 1;
        *(uint4*)(sm + mat * AMATB + rr * AROWB + 144 + ch * 16) =
            make_uint4(0, 0, 0, 0);
    }
    __syncthreads();   // padding visible before any ldmatrix

    // stage Q (rows clamped; invalid q-rows produce unused outputs)
    for (int t = tid; t < 2 * 576; t += 128) {
        const int mat = t / 576, rem = t - mat * 576;
        const int r = rem / 9, ch = rem - r * 9;
        int tr = s0 + q0 + r; if (tr >= T) tr = T - 1;
        const unsigned short* src = mat ? QL : QH;
        cp16(sb + mat * AMATB + (uint32_t)r * AROWB + ch * 16,
             src + (size_t)tr * HD + ch * 8);
    }

    auto issueKV = [&](int kt, int buf) {
        const int k0 = kt * 64;
        const uint32_t dbase = sb + (uint32_t)(2 + buf * 4) * AMATB;
        for (int t = tid; t < 4 * 576; t += 128) {
            const int mat = t / 576, rem = t - mat * 576;
            const int r = rem / 9, ch = rem - r * 9;
            int tr = s0 + k0 + r; if (tr >= T) tr = T - 1;   // clamped; masked later
            const unsigned short* src =
                (mat == 0) ? KH : (mat == 1) ? KL : (mat == 2) ? VH : VL;
            cp16(dbase + (uint32_t)mat * AMATB + (uint32_t)r * AROWB + ch * 16,
                 src + (size_t)tr * HD + ch * 8);
        }
        CP_COMMIT();
    };

    issueKV(0, 0);   // group: Q + KV0

    float oacc[9][4];
#pragma unroll
    for (int i = 0; i < 9; i++)
#pragma unroll
        for (int j = 0; j < 4; j++) oacc[i][j] = 0.f;
    float m0 = -1e30f, m1 = -1e30f, l0 = 0.f, l1 = 0.f;

    const uint32_t sQh = sb, sQl = sb + AMATB;
    const int nkt = (L + 63) >> 6;

    for (int kt = 0; kt < nkt; kt++) {
        CP_WAIT0();
        __syncthreads();
        if (kt + 1 < nkt) issueKV(kt + 1, (kt + 1) & 1);

        const uint32_t stg = sb + (uint32_t)(2 + (kt & 1) * 4) * AMATB;
        const uint32_t sKh = stg, sKl = stg + AMATB;
        const uint32_t sVh = stg + 2 * AMATB, sVl = stg + 3 * AMATB;
        const int k0 = kt * 64;

        // ---- S = Q K^T (3-term split, unscaled) ----
        float s[8][4];
#pragma unroll
        for (int i = 0; i < 8; i++)
#pragma unroll
            for (int j = 0; j < 4; j++) s[i][j] = 0.f;

        const uint32_t qrow = (uint32_t)(wid * 16 + la_row) * AROWB;
#pragma unroll
        for (int ks = 0; ks < 5; ks++) {
            const uint32_t qc = (uint32_t)(ks * 16 + la_k) * 2;
            uint32_t qh[4], ql[4];
            ldm4(sQh + qrow + qc, qh[0], qh[1], qh[2], qh[3]);
            ldm4(sQl + qrow + qc, ql[0], ql[1], ql[2], ql[3]);
            const uint32_t kc = (uint32_t)(ks * 16 + lb_k) * 2;
#pragma unroll
            for (int nt16 = 0; nt16 < 4; nt16++) {
                const uint32_t krow = (uint32_t)(nt16 * 16 + lb_n) * AROWB;
                uint32_t kh[4], kl[4];
                ldm4(sKh + krow + kc, kh[0], kh[1], kh[2], kh[3]);
                ldm4(sKl + krow + kc, kl[0], kl[1], kl[2], kl[3]);
#pragma unroll
                for (int sub = 0; sub < 2; sub++) {
                    float* ss = s[nt16 * 2 + sub];
                    const int jo = sub * 2;
                    mma_bf16(ss[0], ss[1], ss[2], ss[3],
                             qh[0], qh[1], qh[2], qh[3], kh[jo], kh[jo + 1]);
                    mma_bf16(ss[0], ss[1], ss[2], ss[3],
                             qh[0], qh[1], qh[2], qh[3], kl[jo], kl[jo + 1]);
                    mma_bf16(ss[0], ss[1], ss[2], ss[3],
                             ql[0], ql[1], ql[2], ql[3], kh[jo], kh[jo + 1]);
                }
            }
        }

        // ---- scale + mask + online softmax ----
        float mx0 = -1e30f, mx1 = -1e30f;
#pragma unroll
        for (int nt = 0; nt < 8; nt++) {
            const int col = k0 + nt * 8 + qid * 2;
            s[nt][0] *= scale; s[nt][1] *= scale;
            s[nt][2] *= scale; s[nt][3] *= scale;
            if (col >= L)     { s[nt][0] = -1e30f; s[nt][2] = -1e30f; }
            if (col + 1 >= L) { s[nt][1] = -1e30f; s[nt][3] = -1e30f; }
            mx0 = fmaxf(mx0, fmaxf(s[nt][0], s[nt][1]));
            mx1 = fmaxf(mx1, fmaxf(s[nt][2], s[nt][3]));
        }
        mx0 = fmaxf(mx0, __shfl_xor_sync(0xffffffffu, mx0, 1));
        mx0 = fmaxf(mx0, __shfl_xor_sync(0xffffffffu, mx0, 2));
        mx1 = fmaxf(mx1, __shfl_xor_sync(0xffffffffu, mx1, 1));
        mx1 = fmaxf(mx1, __shfl_xor_sync(0xffffffffu, mx1, 2));
        const float mn0 = fmaxf(m0, mx0), mn1 = fmaxf(m1, mx1);
        const float a0 = __expf(m0 - mn0), a1 = __expf(m1 - mn1);
        float ls0 = 0.f, ls1 = 0.f;
#pragma unroll
        for (int nt = 0; nt < 8; nt++) {
            s[nt][0] = __expf(s[nt][0] - mn0); ls0 += s[nt][0];
            s[nt][1] = __expf(s[nt][1] - mn0); ls0 += s[nt][1];
            s[nt][2] = __expf(s[nt][2] - mn1); ls1 += s[nt][2];
            s[nt][3] = __expf(s[nt][3] - mn1); ls1 += s[nt][3];
        }
        ls0 += __shfl_xor_sync(0xffffffffu, ls0, 1);
        ls0 += __shfl_xor_sync(0xffffffffu, ls0, 2);
        ls1 += __shfl_xor_sync(0xffffffffu, ls1, 1);
        ls1 += __shfl_xor_sync(0xffffffffu, ls1, 2);
        l0 = l0 * a0 + ls0;  l1 = l1 * a1 + ls1;
        m0 = mn0;            m1 = mn1;
#pragma unroll
        for (int i = 0; i < 9; i++) {
            oacc[i][0] *= a0; oacc[i][1] *= a0;
            oacc[i][2] *= a1; oacc[i][3] *= a1;
        }

        // ---- O += P V (3-term split; 9 of 10 column groups: d<72) ----
#pragma unroll
        for (int kt2 = 0; kt2 < 4; kt2++) {
            float* t0 = s[kt2 * 2];
            float* t1 = s[kt2 * 2 + 1];
            uint32_t pah[4], pal[4];
            pah[0] = packsplit(t0[0], t0[1], pal[0]);
            pah[1] = packsplit(t0[2], t0[3], pal[1]);
            pah[2] = packsplit(t1[0], t1[1], pal[2]);
            pah[3] = packsplit(t1[2], t1[3], pal[3]);
            const uint32_t vrow = (uint32_t)(kt2 * 16 + la_row) * AROWB
                                + (uint32_t)((lane >> 4) & 1) * 16;
#pragma unroll
            for (int np = 0; np < 5; np++) {
                const uint32_t off = vrow + np * 32;
                uint32_t vh[4], vl[4];
                ldm4t(sVh + off, vh[0], vh[1], vh[2], vh[3]);
                ldm4t(sVl + off, vl[0], vl[1], vl[2], vl[3]);
#pragma unroll
                for (int sub = 0; sub < 2; sub++) {
                    if (np == 4 && sub == 1) continue;   // d 72..79 are zeros
                    float* o = oacc[np * 2 + sub];
                    const int jo = sub * 2;
                    mma_bf16(o[0], o[1], o[2], o[3],
                             pah[0], pah[1], pah[2], pah[3], vh[jo], vh[jo + 1]);
                    mma_bf16(o[0], o[1], o[2], o[3],
                             pah[0], pah[1], pah[2], pah[3], vl[jo], vl[jo + 1]);
                    mma_bf16(o[0], o[1], o[2], o[3],
                             pal[0], pal[1], pal[2], pal[3], vh[jo], vh[jo + 1]);
                }
            }
        }
        // no trailing barrier: next iteration's top barrier orders buffer reuse
    }

    // ---- normalize + store bf16 hi/lo directly (feeds tc_gemm<1>) ----
    const float inv0 = 1.f / l0, inv1 = 1.f / l1;
    const int r0 = q0 + wid * 16 + gid;
    const int r1 = r0 + 8;
#pragma unroll
    for (int np = 0; np < 5; np++) {
#pragma unroll
        for (int sub = 0; sub < 2; sub++) {
            if (np == 4 && sub == 1) continue;
            const int col = np * 16 + sub * 8 + qid * 2;
            float* o = oacc[np * 2 + sub];
            if (r0 < L) {
                const size_t idx = (size_t)(s0 + r0) * EMB + h * HD + col;
                uint32_t lo, hi = packsplit(o[0] * inv0, o[1] * inv0, lo);
                *(uint32_t*)&g_oh[idx] = hi;
                *(uint32_t*)&g_ol[idx] = lo;
            }
            if (r1 < L) {
                const size_t idx = (size_t)(s0 + r1) * EMB + h * HD + col;
                uint32_t lo, hi = packsplit(o[2] * inv1, o[3] * inv1, lo);
                *(uint32_t*)&g_oh[idx] = hi;
                *(uint32_t*)&g_ol[idx] = lo;
            }
        }
    }
}

// ---------------------------------------------------------------------------
extern "C" void kernel_launch(void* const* d_in, const int* in_sizes, int n_in,
                              void* d_out, int out_size)
{
    const float* x    = (const float*)d_in[0];
    const float* wqkv = (const float*)d_in[1];
    const float* bqkv = (const float*)d_in[2];
    const float* wout = (const float*)d_in[3];
    const float* bout = (const float*)d_in[4];
    const int*   cu   = (const int*)d_in[5];

    const int T = in_sizes[0] / EMB;      // 4096
    const int nseq = in_sizes[5] - 1;     // 8

    const int SMEM_GEMM = 2 * STAGEB;     // 81920 B -> 2 CTAs/SM
    cudaFuncSetAttribute(tc_gemm<0>, cudaFuncAttributeMaxDynamicSharedMemorySize, SMEM_GEMM);
    cudaFuncSetAttribute(tc_gemm<1>, cudaFuncAttributeMaxDynamicSharedMemorySize, SMEM_GEMM);

    const int SMEM_ATTN = 10 * AMATB;     // 112640 B -> 2 CTAs/SM
    cudaFuncSetAttribute(attn_mma, cudaFuncAttributeMaxDynamicSharedMemorySize, SMEM_ATTN);

    // 0) fused fp32 -> bf16 hi/lo splits (single launch)
    {
        const int ntot = N4_X + N4_W1 + N4_W2;
        cvt_all<<<(ntot + 255) / 256, 256>>>((const float4*)x,
                                             (const float4*)wqkv,
                                             (const float4*)wout);
    }

    // 1) fused QKV projection (HMMA) -> bf16 hi/lo Q/K/V in [h][t][d]
    dim3 g1(E3 / 128, T / 128);
    tc_gemm<0><<<g1, dim3(256), SMEM_GEMM>>>(bqkv, nullptr, T, E3, EMB);

    // 2) block-diagonal varlen attention (HMMA, cp.async staged) -> g_oh/g_ol
    dim3 ga((T + 63) / 64, NH, nseq);
    attn_mma<<<ga, dim3(128), SMEM_ATTN>>>(cu, T);

    // 3) output projection (HMMA) -> d_out
    dim3 g2(EMB / 128, T / 128);
    tc_gemm<1><<<g2, dim3(256), SMEM_GEMM>>>(bout, (float*)d_out, T, EMB, EMB);
}